// round 1
// baseline (speedup 1.0000x reference)
#include <cuda_runtime.h>
#include <math.h>

#define NNODES 4096
#define NW 128           // adjacency words per row (4096/32)
#define NHEADS 4

// ---------------- scratch (device globals; no allocs allowed) ----------------
__device__ unsigned g_adjbits[NNODES * NW];                 // 2 MB packed mask
__device__ float g_hf[NHEADS * NNODES * 128];               // 8 MB feature buffer (max layer)
__device__ float g_f1[NHEADS * NNODES];
__device__ float g_f2[NHEADS * NNODES];
__device__ float g_E1[NHEADS * NNODES];
__device__ float g_E1s[NHEADS * NNODES];
__device__ float g_E2[NHEADS * NNODES];
__device__ float g_E2s[NHEADS * NNODES];
__device__ float g_cat1[NNODES * 512];
__device__ float g_cat2[NNODES * 256];
__device__ float g_h3[NNODES * 16];

__device__ __forceinline__ float eluf(float v) { return v > 0.f ? v : expm1f(v); }

// ---------------- adjacency bit-pack ----------------
__global__ void pack_adj(const int* __restrict__ adj) {
    int wi = blockIdx.x * blockDim.x + threadIdx.x;   // word index over N*NW
    if (wi >= NNODES * NW) return;
    const int4* p = (const int4*)adj + (size_t)wi * 8;  // 32 ints
    unsigned w = 0;
#pragma unroll
    for (int q = 0; q < 8; q++) {
        int4 v = p[q];
        if (v.x > 0) w |= 1u << (q * 4 + 0);
        if (v.y > 0) w |= 1u << (q * 4 + 1);
        if (v.z > 0) w |= 1u << (q * 4 + 2);
        if (v.w > 0) w |= 1u << (q * 4 + 3);
    }
    g_adjbits[wi] = w;
}

// ---------------- feature GEMM: C[h][n][d] = sum_k A[n][k] * W[h][k][d] ----------------
// SRC: 0 = external A param, 1 = g_cat1, 2 = g_cat2. Output always g_hf.
template<int TN, int TD, int MR, int NC, int SRC>
__global__ __launch_bounds__(256) void gemm_k(const float* __restrict__ Aext,
                                              const float* __restrict__ W,
                                              int K, int Dtot) {
    const int TK = 16;
    __shared__ float As[TK][TN];
    __shared__ float Bs[TK][TD];
    const float* A = (SRC == 0) ? Aext : (SRC == 1 ? g_cat1 : g_cat2);

    int t = threadIdx.x;
    int n0 = blockIdx.x * TN;
    int d0 = blockIdx.y * TD;
    int h  = blockIdx.z;
    const float* Wh = W + (size_t)h * K * Dtot;

    const int rg = t / (TD / NC);
    const int cg = t % (TD / NC);

    float acc[MR][NC];
#pragma unroll
    for (int i = 0; i < MR; i++)
#pragma unroll
        for (int j = 0; j < NC; j++) acc[i][j] = 0.f;

    for (int k0 = 0; k0 < K; k0 += TK) {
        for (int idx = t; idx < TN * (TK / 4); idx += 256) {
            int i_n = idx / (TK / 4);
            int k4  = idx % (TK / 4);
            float4 v = *(const float4*)&A[(size_t)(n0 + i_n) * K + k0 + 4 * k4];
            As[4 * k4 + 0][i_n] = v.x;
            As[4 * k4 + 1][i_n] = v.y;
            As[4 * k4 + 2][i_n] = v.z;
            As[4 * k4 + 3][i_n] = v.w;
        }
        for (int idx = t; idx < TK * (TD / 4); idx += 256) {
            int kk = idx / (TD / 4);
            int j4 = idx % (TD / 4);
            *(float4*)&Bs[kk][4 * j4] =
                *(const float4*)&Wh[(size_t)(k0 + kk) * Dtot + d0 + 4 * j4];
        }
        __syncthreads();
#pragma unroll
        for (int k = 0; k < TK; k++) {
            float a_[MR], b_[NC];
#pragma unroll
            for (int i = 0; i < MR; i++) a_[i] = As[k][rg * MR + i];
#pragma unroll
            for (int j = 0; j < NC; j++) b_[j] = Bs[k][cg * NC + j];
#pragma unroll
            for (int i = 0; i < MR; i++)
#pragma unroll
                for (int j = 0; j < NC; j++)
                    acc[i][j] = fmaf(a_[i], b_[j], acc[i][j]);
        }
        __syncthreads();
    }
    float* Ch = g_hf + (size_t)h * NNODES * Dtot;
#pragma unroll
    for (int i = 0; i < MR; i++)
#pragma unroll
        for (int j = 0; j < NC; j++)
            Ch[(size_t)(n0 + rg * MR + i) * Dtot + d0 + cg * NC + j] = acc[i][j];
}

// ---------------- scores: f1/f2 dot products + precomputed exps ----------------
__global__ __launch_bounds__(256) void scores_k(const float* __restrict__ a, int D, int total) {
    int gid  = blockIdx.x * 8 + (threadIdx.x >> 5);
    int lane = threadIdx.x & 31;
    if (gid >= total) return;
    int h = gid / NNODES, n = gid % NNODES;
    const float* hr = g_hf + ((size_t)h * NNODES + n) * D;
    const float* a1 = a + (size_t)h * 2 * D;
    const float* a2 = a1 + D;
    float s1 = 0.f, s2 = 0.f;
    for (int d = lane; d < D; d += 32) {
        float v = hr[d];
        s1 += v * a1[d];
        s2 += v * a2[d];
    }
#pragma unroll
    for (int o = 16; o; o >>= 1) {
        s1 += __shfl_xor_sync(~0u, s1, o);
        s2 += __shfl_xor_sync(~0u, s2, o);
    }
    if (!lane) {
        int idx = h * NNODES + n;
        g_f1[idx]  = s1;
        g_f2[idx]  = s2;
        g_E1[idx]  = expf(s1);
        g_E1s[idx] = expf(0.2f * s1);
        g_E2[idx]  = expf(s2);
        g_E2s[idx] = expf(0.2f * s2);
    }
}

// ---------------- fused masked-softmax aggregation ----------------
// out[n, head*D + d] = epi( (1/Z) * sum_m mask*w(n,m)*hf[m,d] )
// w = (f1[n]+f2[m] >= 0) ? E1[n]*E2[m] : E1s[n]*E2s[m]
// EPI: 0 -> elu(v + x[n,d]) into g_cat1 ; 1 -> elu(v) into g_cat2 ; 2 -> elu(v) into g_h3
template<int D, int TN, int MR, int NC, int EPI>
__global__ __launch_bounds__(256) void agg_k(const float* __restrict__ resid, int outStride) {
    const int TM = 32;
    __shared__ float hs[TM][D];
    __shared__ float ws[TM][TN + 4];
    __shared__ float Zred[256];
    __shared__ float Zs[TN];

    int t    = threadIdx.x;
    int n0   = blockIdx.x * TN;
    int head = blockIdx.y;
    const int headN = head * NNODES;
    const float* hfh = g_hf + (size_t)headN * D;
    float* out = (EPI == 0) ? g_cat1 : (EPI == 1 ? g_cat2 : g_h3);

    // phase A: fixed row per thread (TN divides 256)
    const int rA = t % TN;
    const int G  = 256 / TN;
    const int g  = t / TN;
    const int MMPT = TM / G;

    float rf1  = g_f1[headN + n0 + rA];
    float rE1  = g_E1[headN + n0 + rA];
    float rE1s = g_E1s[headN + n0 + rA];
    float zacc = 0.f;

    const int rg = t / (D / NC);
    const int cg = t % (D / NC);

    float acc[MR][NC];
#pragma unroll
    for (int i = 0; i < MR; i++)
#pragma unroll
        for (int j = 0; j < NC; j++) acc[i][j] = 0.f;

    for (int mt = 0; mt < NNODES / TM; mt++) {
        int m0 = mt * TM;
        // load feature tile
        for (int idx = t; idx < TM * D / 4; idx += 256) {
            int m  = idx / (D / 4);
            int dd = idx % (D / 4);
            *(float4*)&hs[m][4 * dd] = *(const float4*)&hfh[(size_t)(m0 + m) * D + 4 * dd];
        }
        // phase A: weights
        unsigned aw = g_adjbits[(size_t)(n0 + rA) * NW + mt];
#pragma unroll
        for (int j = 0; j < MMPT; j++) {
            int mm = g + G * j;
            float w = 0.f;
            if ((aw >> mm) & 1u) {
                float s = rf1 + g_f2[headN + m0 + mm];
                w = (s >= 0.f) ? rE1 * g_E2[headN + m0 + mm]
                               : rE1s * g_E2s[headN + m0 + mm];
            }
            ws[mm][rA] = w;
            zacc += w;
        }
        __syncthreads();
        // phase B: GEMM micro-kernel
#pragma unroll
        for (int k = 0; k < TM; k++) {
            float a_[MR], b_[NC];
#pragma unroll
            for (int i = 0; i < MR; i++) a_[i] = ws[k][rg * MR + i];
#pragma unroll
            for (int j = 0; j < NC; j++) b_[j] = hs[k][cg * NC + j];
#pragma unroll
            for (int i = 0; i < MR; i++)
#pragma unroll
                for (int j = 0; j < NC; j++)
                    acc[i][j] = fmaf(a_[i], b_[j], acc[i][j]);
        }
        __syncthreads();
    }

    // Z reduction (G partials per row)
    Zred[t] = zacc;
    __syncthreads();
    if (t < TN) {
        float z = 0.f;
#pragma unroll
        for (int q = 0; q < G; q++) z += Zred[t + q * TN];
        Zs[t] = 1.f / z;
    }
    __syncthreads();

#pragma unroll
    for (int i = 0; i < MR; i++) {
        int row    = n0 + rg * MR + i;
        float zinv = Zs[rg * MR + i];
#pragma unroll
        for (int j = 0; j < NC; j++) {
            int d   = cg * NC + j;
            float v = acc[i][j] * zinv;
            if (EPI == 0) v = eluf(v + resid[(size_t)row * 128 + d]);
            else          v = eluf(v);
            out[(size_t)row * outStride + head * D + d] = v;
        }
    }
}

// ---------------- final log-softmax over 16 outputs ----------------
__global__ __launch_bounds__(256) void logsoftmax_k(float* __restrict__ out) {
    int n    = blockIdx.x * 8 + (threadIdx.x >> 5);
    int lane = threadIdx.x & 31;
    if (n >= NNODES) return;
    float v = (lane < 16) ? g_h3[n * 16 + lane] : -INFINITY;
    float m = v;
#pragma unroll
    for (int o = 16; o; o >>= 1) m = fmaxf(m, __shfl_xor_sync(~0u, m, o));
    float e = (lane < 16) ? expf(v - m) : 0.f;
    float s = e;
#pragma unroll
    for (int o = 16; o; o >>= 1) s += __shfl_xor_sync(~0u, s, o);
    if (lane < 16) out[n * 16 + lane] = v - m - logf(s);
}

// ---------------- launch ----------------
extern "C" void kernel_launch(void* const* d_in, const int* in_sizes, int n_in,
                              void* d_out, int out_size) {
    const float* x     = (const float*)d_in[0];
    const int*   adj   = (const int*)d_in[1];
    const float* W_in  = (const float*)d_in[2];
    const float* a_in  = (const float*)d_in[3];
    const float* W_hid = (const float*)d_in[4];
    const float* a_hid = (const float*)d_in[5];
    const float* W_out = (const float*)d_in[6];
    const float* a_out = (const float*)d_in[7];
    float* out = (float*)d_out;

    pack_adj<<<(NNODES * NW + 255) / 256, 256>>>(adj);

    // Layer 1: D=128, 4 heads, identity residual, concat -> g_cat1 [N,512]
    gemm_k<64, 64, 4, 4, 0><<<dim3(64, 2, 4), 256>>>(x, W_in, 128, 128);
    scores_k<<<(NHEADS * NNODES) / 8, 256>>>(a_in, 128, NHEADS * NNODES);
    agg_k<128, 64, 4, 8, 0><<<dim3(64, 4), 256>>>(x, 512);

    // Layer 2: D=64, 4 heads, concat -> g_cat2 [N,256]
    gemm_k<64, 64, 4, 4, 1><<<dim3(64, 1, 4), 256>>>(nullptr, W_hid, 512, 64);
    scores_k<<<(NHEADS * NNODES) / 8, 256>>>(a_hid, 64, NHEADS * NNODES);
    agg_k<64, 128, 8, 4, 1><<<dim3(32, 4), 256>>>(nullptr, 256);

    // Layer 3: D=16, 1 head -> g_h3 [N,16]
    gemm_k<64, 16, 4, 1, 2><<<dim3(64, 1, 1), 256>>>(nullptr, W_out, 256, 16);
    scores_k<<<NNODES / 8, 256>>>(a_out, 16, NNODES);
    agg_k<16, 32, 2, 1, 2><<<dim3(128, 1), 256>>>(nullptr, 16);

    logsoftmax_k<<<NNODES / 8, 256>>>(out);
}

// round 2
// speedup vs baseline: 1.2239x; 1.2239x over previous
#include <cuda_runtime.h>
#include <math.h>

#define NNODES 4096
#define NW 128           // adjacency words per row (4096/32)
#define NHEADS 4

typedef unsigned long long ull;

// ---------------- scratch (device globals; no allocs allowed) ----------------
__device__ unsigned g_adjbits[NNODES * NW];                 // 2 MB packed mask
__device__ float g_hf[NHEADS * NNODES * 128];               // 8 MB feature buffer (max layer)
__device__ float g_f1[NHEADS * NNODES];
__device__ float g_f2[NHEADS * NNODES];
__device__ float g_E1[NHEADS * NNODES];
__device__ float g_E1s[NHEADS * NNODES];
__device__ float g_E2[NHEADS * NNODES];
__device__ float g_E2s[NHEADS * NNODES];
__device__ float g_cat1[NNODES * 512];
__device__ float g_cat2[NNODES * 256];
__device__ float g_h3[NNODES * 16];
// L2 m-split partials: [2 splits][4 heads][4096 n][64 d] + Z partials
__device__ float g_p2[2 * NHEADS * NNODES * 64];
__device__ float g_pz2[2 * NHEADS * NNODES];

__device__ __forceinline__ float eluf(float v) { return v > 0.f ? v : expm1f(v); }

__device__ __forceinline__ ull dupf(float v) {
    ull r;
    asm("mov.b64 %0, {%1, %1};" : "=l"(r) : "f"(v));
    return r;
}
__device__ __forceinline__ void ffma2(ull& acc, ull a, ull b) {
    asm("fma.rn.f32x2 %0, %1, %2, %0;" : "+l"(acc) : "l"(a), "l"(b));
}
__device__ __forceinline__ float2 unpack2(ull v) {
    float2 r;
    asm("mov.b64 {%0, %1}, %2;" : "=f"(r.x), "=f"(r.y) : "l"(v));
    return r;
}

// ---------------- adjacency bit-pack ----------------
__global__ void pack_adj(const int* __restrict__ adj) {
    int wi = blockIdx.x * blockDim.x + threadIdx.x;
    if (wi >= NNODES * NW) return;
    const int4* p = (const int4*)adj + (size_t)wi * 8;
    unsigned w = 0;
#pragma unroll
    for (int q = 0; q < 8; q++) {
        int4 v = p[q];
        if (v.x > 0) w |= 1u << (q * 4 + 0);
        if (v.y > 0) w |= 1u << (q * 4 + 1);
        if (v.z > 0) w |= 1u << (q * 4 + 2);
        if (v.w > 0) w |= 1u << (q * 4 + 3);
    }
    g_adjbits[wi] = w;
}

// ---------------- feature GEMM: C[h][n][d] = sum_k A[n][k] * W[h][k][d] ----------------
template<int TN, int TD, int MR, int NC, int SRC>
__global__ __launch_bounds__(256) void gemm_k(const float* __restrict__ Aext,
                                              const float* __restrict__ W,
                                              int K, int Dtot) {
    const int TK = 16;
    __shared__ float As[TK][TN];
    __shared__ float Bs[TK][TD];
    const float* A = (SRC == 0) ? Aext : (SRC == 1 ? g_cat1 : g_cat2);

    int t = threadIdx.x;
    int n0 = blockIdx.x * TN;
    int d0 = blockIdx.y * TD;
    int h  = blockIdx.z;
    const float* Wh = W + (size_t)h * K * Dtot;

    const int rg = t / (TD / NC);
    const int cg = t % (TD / NC);

    float acc[MR][NC];
#pragma unroll
    for (int i = 0; i < MR; i++)
#pragma unroll
        for (int j = 0; j < NC; j++) acc[i][j] = 0.f;

    for (int k0 = 0; k0 < K; k0 += TK) {
        for (int idx = t; idx < TN * (TK / 4); idx += 256) {
            int i_n = idx / (TK / 4);
            int k4  = idx % (TK / 4);
            float4 v = *(const float4*)&A[(size_t)(n0 + i_n) * K + k0 + 4 * k4];
            As[4 * k4 + 0][i_n] = v.x;
            As[4 * k4 + 1][i_n] = v.y;
            As[4 * k4 + 2][i_n] = v.z;
            As[4 * k4 + 3][i_n] = v.w;
        }
        for (int idx = t; idx < TK * (TD / 4); idx += 256) {
            int kk = idx / (TD / 4);
            int j4 = idx % (TD / 4);
            *(float4*)&Bs[kk][4 * j4] =
                *(const float4*)&Wh[(size_t)(k0 + kk) * Dtot + d0 + 4 * j4];
        }
        __syncthreads();
#pragma unroll
        for (int k = 0; k < TK; k++) {
            float a_[MR], b_[NC];
#pragma unroll
            for (int i = 0; i < MR; i++) a_[i] = As[k][rg * MR + i];
#pragma unroll
            for (int j = 0; j < NC; j++) b_[j] = Bs[k][cg * NC + j];
#pragma unroll
            for (int i = 0; i < MR; i++)
#pragma unroll
                for (int j = 0; j < NC; j++)
                    acc[i][j] = fmaf(a_[i], b_[j], acc[i][j]);
        }
        __syncthreads();
    }
    float* Ch = g_hf + (size_t)h * NNODES * Dtot;
#pragma unroll
    for (int i = 0; i < MR; i++)
#pragma unroll
        for (int j = 0; j < NC; j++)
            Ch[(size_t)(n0 + rg * MR + i) * Dtot + d0 + cg * NC + j] = acc[i][j];
}

// ---------------- scores: f1/f2 dot products + precomputed exps ----------------
__global__ __launch_bounds__(256) void scores_k(const float* __restrict__ a, int D, int total) {
    int gid  = blockIdx.x * 8 + (threadIdx.x >> 5);
    int lane = threadIdx.x & 31;
    if (gid >= total) return;
    int h = gid / NNODES, n = gid % NNODES;
    const float* hr = g_hf + ((size_t)h * NNODES + n) * D;
    const float* a1 = a + (size_t)h * 2 * D;
    const float* a2 = a1 + D;
    float s1 = 0.f, s2 = 0.f;
    for (int d = lane; d < D; d += 32) {
        float v = hr[d];
        s1 += v * a1[d];
        s2 += v * a2[d];
    }
#pragma unroll
    for (int o = 16; o; o >>= 1) {
        s1 += __shfl_xor_sync(~0u, s1, o);
        s2 += __shfl_xor_sync(~0u, s2, o);
    }
    if (!lane) {
        int idx = h * NNODES + n;
        g_f1[idx]  = s1;
        g_f2[idx]  = s2;
        g_E1[idx]  = expf(s1);
        g_E1s[idx] = expf(0.2f * s1);
        g_E2[idx]  = expf(s2);
        g_E2s[idx] = expf(0.2f * s2);
    }
}

// ---------------- fused masked-softmax aggregation v2 ----------------
// 128 threads. TM=32 m-tile, double-buffered, f32x2 math packed along rows.
// EPI: 0 -> elu(v + resid) to g_cat1 ; 1 -> elu(v) to g_cat2 ; 2 -> elu(v) to g_h3
//      3 -> raw partials to g_p2/g_pz2 (m-split mode)
template<int D, int DC, int TN, int MR, int NC, int EPI, int MSPLIT>
__global__ __launch_bounds__(128) void agg_k(const float* __restrict__ resid, int outStride) {
    const int TM  = 32;
    const int PAD = 2;                       // keeps row stride even (8B-aligned pairs)
    __shared__ __align__(16) float hs[2][TM][DC];
    __shared__ __align__(16) float ws[2][TM][TN + PAD];
    __shared__ float Zred[128];
    __shared__ float Zs[TN];

    const int t    = threadIdx.x;
    const int n0   = blockIdx.x * TN;
    const int head = blockIdx.y;
    const int dc0  = (MSPLIT == 1) ? blockIdx.z * DC : 0;
    const int ms   = (MSPLIT > 1) ? blockIdx.z : 0;
    const int NT   = (NNODES / TM) / MSPLIT;
    const int mtb  = ms * NT;

    const int headN = head * NNODES;
    const float* hfh = g_hf + (size_t)headN * D;

    // phase-A row assignment
    const int rA = t % TN;
    const int G  = 128 / TN;
    const int g  = t / TN;
    const int MMPT = TM / G;

    const float rf1  = g_f1[headN + n0 + rA];
    const float rE1  = g_E1[headN + n0 + rA];
    const float rE1s = g_E1s[headN + n0 + rA];
    float zacc = 0.f;

    // phase-B micro-tile assignment
    const int rg = t / (DC / NC);
    const int cg = t % (DC / NC);

    ull acc[MR / 2][NC];
#pragma unroll
    for (int i = 0; i < MR / 2; i++)
#pragma unroll
        for (int j = 0; j < NC; j++) acc[i][j] = 0ull;

    // ---- fill helper (as a lambda): loads tile `wti` into buffer `buf` ----
    auto fill = [&](int wti, int buf) {
        int m0 = wti * TM;
        // feature tile
        for (int idx = t; idx < TM * (DC / 4); idx += 128) {
            int m  = idx / (DC / 4);
            int dd = idx % (DC / 4);
            *(float4*)&hs[buf][m][4 * dd] =
                *(const float4*)&hfh[(size_t)(m0 + m) * D + dc0 + 4 * dd];
        }
        // weights
        unsigned aw = g_adjbits[(size_t)(n0 + rA) * NW + wti];
#pragma unroll
        for (int j = 0; j < MMPT; j++) {
            int mm = g + G * j;
            float w = 0.f;
            if ((aw >> mm) & 1u) {
                float s = rf1 + g_f2[headN + m0 + mm];
                w = (s >= 0.f) ? rE1 * g_E2[headN + m0 + mm]
                               : rE1s * g_E2s[headN + m0 + mm];
            }
            ws[buf][mm][rA] = w;
            zacc += w;
        }
    };

    fill(mtb, 0);
    __syncthreads();

    for (int mt = 0; mt < NT; mt++) {
        int cur = mt & 1;
        if (mt + 1 < NT) fill(mtb + mt + 1, cur ^ 1);
#pragma unroll
        for (int k = 0; k < TM; k++) {
            ull a2[MR / 2];
#pragma unroll
            for (int i = 0; i < MR / 2; i++)
                a2[i] = *(const ull*)&ws[cur][k][rg * MR + 2 * i];
            float bv[NC];
            if (NC == 4) {
                float4 b4 = *(const float4*)&hs[cur][k][cg * 4];
                bv[0] = b4.x; bv[1] = b4.y; bv[2] = b4.z; bv[3] = b4.w;
            } else {
#pragma unroll
                for (int j = 0; j < NC; j++) bv[j] = hs[cur][k][cg * NC + j];
            }
#pragma unroll
            for (int j = 0; j < NC; j++) {
                ull bb = dupf(bv[j]);
#pragma unroll
                for (int i = 0; i < MR / 2; i++) ffma2(acc[i][j], a2[i], bb);
            }
        }
        __syncthreads();
    }

    // Z reduction (G partials per row)
    Zred[t] = zacc;
    __syncthreads();

    if (EPI == 3) {
        // raw partials out
        if (t < TN) {
            float z = 0.f;
#pragma unroll
            for (int q = 0; q < G; q++) z += Zred[t + q * TN];
            g_pz2[(size_t)(ms * NHEADS + head) * NNODES + n0 + t] = z;
        }
        float* P = g_p2 + (size_t)(ms * NHEADS + head) * NNODES * 64;
#pragma unroll
        for (int i = 0; i < MR / 2; i++) {
            int r0 = n0 + rg * MR + 2 * i;
#pragma unroll
            for (int j = 0; j < NC; j++) {
                float2 v = unpack2(acc[i][j]);
                int d = cg * NC + j;
                P[(size_t)r0 * 64 + d]       = v.x;
                P[(size_t)(r0 + 1) * 64 + d] = v.y;
            }
        }
        return;
    }

    if (t < TN) {
        float z = 0.f;
#pragma unroll
        for (int q = 0; q < G; q++) z += Zred[t + q * TN];
        Zs[t] = 1.f / z;
    }
    __syncthreads();

    float* out = (EPI == 0) ? g_cat1 : (EPI == 1 ? g_cat2 : g_h3);
#pragma unroll
    for (int i = 0; i < MR / 2; i++) {
        int lr0 = rg * MR + 2 * i;
        float zi0 = Zs[lr0], zi1 = Zs[lr0 + 1];
#pragma unroll
        for (int j = 0; j < NC; j++) {
            float2 v = unpack2(acc[i][j]);
            int d = cg * NC + j;
            float v0 = v.x * zi0, v1 = v.y * zi1;
            int row0 = n0 + lr0;
            if (EPI == 0) {
                v0 = eluf(v0 + resid[(size_t)row0 * 128 + dc0 + d]);
                v1 = eluf(v1 + resid[(size_t)(row0 + 1) * 128 + dc0 + d]);
            } else {
                v0 = eluf(v0);
                v1 = eluf(v1);
            }
            out[(size_t)row0 * outStride + head * D + dc0 + d]       = v0;
            out[(size_t)(row0 + 1) * outStride + head * D + dc0 + d] = v1;
        }
    }
}

// ---------------- combine L2 partials -> g_cat2 ----------------
__global__ __launch_bounds__(256) void combine2_k() {
    int e = blockIdx.x * 256 + threadIdx.x;          // float4 index, total 4*4096*16
    int head = e >> 16;                               // 65536 float4 per head
    int r = e & 65535;
    int n  = r >> 4;
    int d4 = r & 15;
    const float4* P = (const float4*)g_p2;
    float4 a = P[((size_t)head * NNODES + n) * 16 + d4];
    float4 b = P[((size_t)(NHEADS + head) * NNODES + n) * 16 + d4];
    float zi = 1.f / (g_pz2[(size_t)head * NNODES + n] +
                      g_pz2[(size_t)(NHEADS + head) * NNODES + n]);
    float4 v;
    v.x = eluf((a.x + b.x) * zi);
    v.y = eluf((a.y + b.y) * zi);
    v.z = eluf((a.z + b.z) * zi);
    v.w = eluf((a.w + b.w) * zi);
    ((float4*)g_cat2)[((size_t)n * NHEADS + head) * 16 + d4] = v;
}

// ---------------- final log-softmax over 16 outputs ----------------
__global__ __launch_bounds__(256) void logsoftmax_k(float* __restrict__ out) {
    int n    = blockIdx.x * 8 + (threadIdx.x >> 5);
    int lane = threadIdx.x & 31;
    if (n >= NNODES) return;
    float v = (lane < 16) ? g_h3[n * 16 + lane] : -INFINITY;
    float m = v;
#pragma unroll
    for (int o = 16; o; o >>= 1) m = fmaxf(m, __shfl_xor_sync(~0u, m, o));
    float e = (lane < 16) ? expf(v - m) : 0.f;
    float s = e;
#pragma unroll
    for (int o = 16; o; o >>= 1) s += __shfl_xor_sync(~0u, s, o);
    if (lane < 16) out[n * 16 + lane] = v - m - logf(s);
}

// ---------------- launch ----------------
extern "C" void kernel_launch(void* const* d_in, const int* in_sizes, int n_in,
                              void* d_out, int out_size) {
    const float* x     = (const float*)d_in[0];
    const int*   adj   = (const int*)d_in[1];
    const float* W_in  = (const float*)d_in[2];
    const float* a_in  = (const float*)d_in[3];
    const float* W_hid = (const float*)d_in[4];
    const float* a_hid = (const float*)d_in[5];
    const float* W_out = (const float*)d_in[6];
    const float* a_out = (const float*)d_in[7];
    float* out = (float*)d_out;

    pack_adj<<<(NNODES * NW + 255) / 256, 256>>>(adj);

    // Layer 1: D=128, 4 heads, residual, concat -> g_cat1 [N,512]; D split in 2
    gemm_k<64, 64, 4, 4, 0><<<dim3(64, 2, 4), 256>>>(x, W_in, 128, 128);
    scores_k<<<(NHEADS * NNODES) / 8, 256>>>(a_in, 128, NHEADS * NNODES);
    agg_k<128, 64, 64, 8, 4, 0, 1><<<dim3(64, 4, 2), 128>>>(x, 512);

    // Layer 2: D=64, 4 heads, m-split in 2 with partial combine -> g_cat2 [N,256]
    gemm_k<64, 64, 4, 4, 1><<<dim3(64, 1, 4), 256>>>(nullptr, W_hid, 512, 64);
    scores_k<<<(NHEADS * NNODES) / 8, 256>>>(a_hid, 64, NHEADS * NNODES);
    agg_k<64, 64, 64, 8, 4, 3, 2><<<dim3(64, 4, 2), 128>>>(nullptr, 0);
    combine2_k<<<1024, 256>>>();

    // Layer 3: D=16, 1 head -> g_h3 [N,16]
    gemm_k<64, 16, 4, 1, 2><<<dim3(64, 1, 1), 256>>>(nullptr, W_out, 256, 16);
    scores_k<<<NNODES / 8, 256>>>(a_out, 16, NNODES);
    agg_k<16, 16, 32, 2, 2, 2, 1><<<dim3(128, 1, 1), 128>>>(nullptr, 16);

    logsoftmax_k<<<NNODES / 8, 256>>>(out);
}

// round 5
// speedup vs baseline: 1.6014x; 1.3084x over previous
#include <cuda_runtime.h>
#include <cuda_bf16.h>
#include <cstdint>
#include <math.h>

#define NNODES 4096
#define NW 128
#define NHEADS 4

typedef unsigned long long ull;

// ---------------- scratch ----------------
__device__ unsigned g_adjbits[NNODES * NW];
__device__ float g_hf[NHEADS * NNODES * 128];
__device__ float g_f1[NHEADS * NNODES];
__device__ float g_f2[NHEADS * NNODES];
__device__ float g_E1[NHEADS * NNODES];
__device__ float g_E1s[NHEADS * NNODES];
__device__ float g_E2[NHEADS * NNODES];
__device__ float g_E2s[NHEADS * NNODES];
__device__ float g_cat1[NNODES * 512];
__device__ float g_cat2[NNODES * 256];
__device__ float g_h3[NNODES * 16];
__device__ __nv_bfloat16 g_hTb_hi[NHEADS * 128 * NNODES];   // [h][d][m]
__device__ __nv_bfloat16 g_hTb_lo[NHEADS * 128 * NNODES];

__device__ __forceinline__ float eluf(float v) { return v > 0.f ? v : expm1f(v); }

__device__ __forceinline__ uint32_t smem_u32(const void* p) {
    uint32_t a;
    asm("{ .reg .u64 t; cvta.to.shared.u64 t, %1; cvt.u32.u64 %0, t; }" : "=r"(a) : "l"(p));
    return a;
}

#define CP16(dst, src) \
    asm volatile("cp.async.cg.shared.global [%0], [%1], 16;" :: "r"(dst), "l"(src))
#define CP_COMMIT() asm volatile("cp.async.commit_group;" ::: "memory")
#define CP_WAIT(n)  asm volatile("cp.async.wait_group %0;" :: "n"(n) : "memory")

#define LDSM4(r, a)                                                            \
    asm volatile("ldmatrix.sync.aligned.m8n8.x4.shared.b16 {%0,%1,%2,%3}, [%4];" \
        : "=r"((r)[0]), "=r"((r)[1]), "=r"((r)[2]), "=r"((r)[3]) : "r"(a))

__device__ __forceinline__ void mma_bf16(float* c, uint32_t a0, uint32_t a1,
                                         uint32_t a2, uint32_t a3,
                                         uint32_t b0, uint32_t b1) {
    asm volatile(
        "mma.sync.aligned.m16n8k16.row.col.f32.bf16.bf16.f32 "
        "{%0,%1,%2,%3}, {%4,%5,%6,%7}, {%8,%9}, {%0,%1,%2,%3};"
        : "+f"(c[0]), "+f"(c[1]), "+f"(c[2]), "+f"(c[3])
        : "r"(a0), "r"(a1), "r"(a2), "r"(a3), "r"(b0), "r"(b1));
}

// ---------------- adjacency bit-pack ----------------
__global__ void pack_adj(const int* __restrict__ adj) {
    int wi = blockIdx.x * blockDim.x + threadIdx.x;
    if (wi >= NNODES * NW) return;
    const int4* p = (const int4*)adj + (size_t)wi * 8;
    unsigned w = 0;
#pragma unroll
    for (int q = 0; q < 8; q++) {
        int4 v = p[q];
        if (v.x > 0) w |= 1u << (q * 4 + 0);
        if (v.y > 0) w |= 1u << (q * 4 + 1);
        if (v.z > 0) w |= 1u << (q * 4 + 2);
        if (v.w > 0) w |= 1u << (q * 4 + 3);
    }
    g_adjbits[wi] = w;
}

// ---------------- feature GEMM ----------------
template<int TN, int TD, int MR, int NC, int SRC>
__global__ __launch_bounds__(256) void gemm_k(const float* __restrict__ Aext,
                                              const float* __restrict__ W,
                                              int K, int Dtot) {
    const int TK = 16;
    __shared__ float As[TK][TN];
    __shared__ float Bs[TK][TD];
    const float* A = (SRC == 0) ? Aext : (SRC == 1 ? g_cat1 : g_cat2);

    int t = threadIdx.x;
    int n0 = blockIdx.x * TN;
    int d0 = blockIdx.y * TD;
    int h  = blockIdx.z;
    const float* Wh = W + (size_t)h * K * Dtot;
    const int rg = t / (TD / NC);
    const int cg = t % (TD / NC);

    float acc[MR][NC];
#pragma unroll
    for (int i = 0; i < MR; i++)
#pragma unroll
        for (int j = 0; j < NC; j++) acc[i][j] = 0.f;

    for (int k0 = 0; k0 < K; k0 += TK) {
        for (int idx = t; idx < TN * (TK / 4); idx += 256) {
            int i_n = idx / (TK / 4);
            int k4  = idx % (TK / 4);
            float4 v = *(const float4*)&A[(size_t)(n0 + i_n) * K + k0 + 4 * k4];
            As[4 * k4 + 0][i_n] = v.x;
            As[4 * k4 + 1][i_n] = v.y;
            As[4 * k4 + 2][i_n] = v.z;
            As[4 * k4 + 3][i_n] = v.w;
        }
        for (int idx = t; idx < TK * (TD / 4); idx += 256) {
            int kk = idx / (TD / 4);
            int j4 = idx % (TD / 4);
            *(float4*)&Bs[kk][4 * j4] =
                *(const float4*)&Wh[(size_t)(k0 + kk) * Dtot + d0 + 4 * j4];
        }
        __syncthreads();
#pragma unroll
        for (int k = 0; k < TK; k++) {
            float a_[MR], b_[NC];
#pragma unroll
            for (int i = 0; i < MR; i++) a_[i] = As[k][rg * MR + i];
#pragma unroll
            for (int j = 0; j < NC; j++) b_[j] = Bs[k][cg * NC + j];
#pragma unroll
            for (int i = 0; i < MR; i++)
#pragma unroll
                for (int j = 0; j < NC; j++)
                    acc[i][j] = fmaf(a_[i], b_[j], acc[i][j]);
        }
        __syncthreads();
    }
    float* Ch = g_hf + (size_t)h * NNODES * Dtot;
#pragma unroll
    for (int i = 0; i < MR; i++)
#pragma unroll
        for (int j = 0; j < NC; j++)
            Ch[(size_t)(n0 + rg * MR + i) * Dtot + d0 + cg * NC + j] = acc[i][j];
}

// ---------------- scores ----------------
__global__ __launch_bounds__(256) void scores_k(const float* __restrict__ a, int D, int total) {
    int gid  = blockIdx.x * 8 + (threadIdx.x >> 5);
    int lane = threadIdx.x & 31;
    if (gid >= total) return;
    int h = gid / NNODES, n = gid % NNODES;
    const float* hr = g_hf + ((size_t)h * NNODES + n) * D;
    const float* a1 = a + (size_t)h * 2 * D;
    const float* a2 = a1 + D;
    float s1 = 0.f, s2 = 0.f;
    for (int d = lane; d < D; d += 32) {
        float v = hr[d];
        s1 += v * a1[d];
        s2 += v * a2[d];
    }
#pragma unroll
    for (int o = 16; o; o >>= 1) {
        s1 += __shfl_xor_sync(~0u, s1, o);
        s2 += __shfl_xor_sync(~0u, s2, o);
    }
    if (!lane) {
        int idx = h * NNODES + n;
        g_f1[idx]  = s1;
        g_f2[idx]  = s2;
        g_E1[idx]  = expf(s1);
        g_E1s[idx] = expf(0.2f * s1);
        g_E2[idx]  = expf(s2);
        g_E2s[idx] = expf(0.2f * s2);
    }
}

// ---------------- transpose + bf16 split: g_hf[h][n][d] -> g_hTb_{hi,lo}[h][d][n] ----------------
template<int D>
__global__ __launch_bounds__(256) void transpose_split_k() {
    __shared__ float ts[32][33];
    int t  = threadIdx.x;
    int nt = blockIdx.x, dt = blockIdx.y, h = blockIdx.z;
    int r0 = t / 32, c = t % 32;
#pragma unroll
    for (int p = 0; p < 4; p++) {
        int r = p * 8 + r0;
        ts[r][c] = g_hf[((size_t)h * NNODES + nt * 32 + r) * D + dt * 32 + c];
    }
    __syncthreads();
#pragma unroll
    for (int p = 0; p < 4; p++) {
        int dr = p * 8 + r0;
        float v = ts[c][dr];
        __nv_bfloat16 hi = __float2bfloat16(v);
        float lo = v - __bfloat162float(hi);
        size_t addr = ((size_t)h * D + dt * 32 + dr) * NNODES + nt * 32 + c;
        g_hTb_hi[addr] = hi;
        g_hTb_lo[addr] = __float2bfloat16(lo);
    }
}

// ---------------- mma.sync masked-softmax aggregation ----------------
// CTA: 128 n-rows x D cols, head = blockIdx.y. 8 warps = 4 Mgroups x 2 Ngroups.
// K-chunk 64, double-buffered cp.async; A (weights) built in registers; 3-pass bf16.
template<int D>
__global__ __launch_bounds__(256, 1) void aggM_k(const float* __restrict__ resid) {
    constexpr int NCOLW = D / 2;         // cols per warp
    constexpr int NTN   = NCOLW / 8;     // 8x8 n-tiles per warp
    constexpr int TMC   = 64;            // m per chunk
    constexpr int NCH   = NNODES / TMC;
    const int O_BL  = D * 288;           // hi region size = 2 bufs * D * 72 * 2B
    const int O_F2  = 2 * D * 288;
    const int O_E2  = O_F2 + 512;
    const int O_E2S = O_E2 + 512;
    const int O_ZS  = O_E2S + 512;

    extern __shared__ __align__(16) char sm[];
    const uint32_t sb = smem_u32(sm);
    float* Zs = (float*)(sm + O_ZS);

    const int t = threadIdx.x, lane = t & 31, wid = t >> 5;
    const int Mg = wid & 3, Ng = wid >> 2;
    const int head = blockIdx.y, n0 = blockIdx.x * 128;
    const int headN = head * NNODES;
    const int rq = lane >> 2;

    // per-thread row constants (4 rows: +0,+8,+16,+24)
    float f1r[4], E1r[4], E1sr[4];
    const unsigned* adjrow[4];
#pragma unroll
    for (int i = 0; i < 4; i++) {
        int r = Mg * 32 + rq + (i & 1) * 8 + (i >> 1) * 16;
        f1r[i]  = g_f1[headN + n0 + r];
        E1r[i]  = g_E1[headN + n0 + r];
        E1sr[i] = g_E1s[headN + n0 + r];
        adjrow[i] = &g_adjbits[(size_t)(n0 + r) * NW];
    }

    float acc[2][NTN][4];
#pragma unroll
    for (int a = 0; a < 2; a++)
#pragma unroll
        for (int b = 0; b < NTN; b++)
#pragma unroll
            for (int cq = 0; cq < 4; cq++) acc[a][b][cq] = 0.f;
    float zacc[4] = {0.f, 0.f, 0.f, 0.f};

    auto fill = [&](int chunk, int buf) {
        for (int idx = t; idx < D * 8; idx += 256) {
            int row = idx >> 3, c8 = idx & 7;
            uint32_t dst = sb + (uint32_t)(((buf * D + row) * 72 + c8 * 8) * 2);
            size_t s = ((size_t)(head * D + row)) * NNODES + chunk * TMC + c8 * 8;
            CP16(dst, (const void*)(g_hTb_hi + s));
            CP16(dst + O_BL, (const void*)(g_hTb_lo + s));
        }
        if (t < 48) {
            int a = t >> 4, q = t & 15;
            const float* s = (a == 0 ? g_f2 : a == 1 ? g_E2 : g_E2s) +
                             headN + chunk * TMC + q * 4;
            uint32_t dst = sb + (uint32_t)((a == 0 ? O_F2 : a == 1 ? O_E2 : O_E2S) +
                                           buf * 256 + q * 16);
            CP16(dst, (const void*)s);
        }
    };

    ull amask[4], amaskN[4];
#pragma unroll
    for (int i = 0; i < 4; i++) { amask[i] = *(const ull*)(adjrow[i]); amaskN[i] = amask[i]; }

    fill(0, 0);
    CP_COMMIT();

    const int k0 = (lane & 3) * 2;
    const int g2 = lane >> 3, rin = lane & 7;

    for (int c = 0; c < NCH; c++) {
        const int buf = c & 1;
        if (c + 1 < NCH) { fill(c + 1, buf ^ 1); CP_COMMIT(); CP_WAIT(1); }
        else             { CP_WAIT(0); }
        __syncthreads();
        if (c + 1 < NCH) {
#pragma unroll
            for (int i = 0; i < 4; i++)
                amaskN[i] = *(const ull*)(adjrow[i] + 2 * (c + 1));
        }

        const float* f2c  = (const float*)(sm + O_F2  + buf * 256);
        const float* E2c  = (const float*)(sm + O_E2  + buf * 256);
        const float* E2sc = (const float*)(sm + O_E2S + buf * 256);

#pragma unroll
        for (int kt = 0; kt < 4; kt++) {
            float f2v[4], e2v[4], e2sv[4];
#pragma unroll
            for (int q = 0; q < 4; q++) {
                int mloc = kt * 16 + (q >> 1) * 8 + k0 + (q & 1);
                f2v[q] = f2c[mloc]; e2v[q] = E2c[mloc]; e2sv[q] = E2sc[mloc];
            }
            uint32_t aH[2][4], aL[2][4];
#pragma unroll
            for (int i = 0; i < 4; i++) {
                const int Mt = i >> 1, rh = i & 1;
                float w[4];
#pragma unroll
                for (int q = 0; q < 4; q++) {
                    float s = f1r[i] + f2v[q];
                    w[q] = (s >= 0.f) ? E1r[i] * e2v[q] : E1sr[i] * e2sv[q];
                }
                unsigned mb = (unsigned)(amask[i] >> (kt * 16 + k0));
                if (!(mb & 1u)) w[0] = 0.f;
                if (!(mb & 2u)) w[1] = 0.f;
                if (!((mb >> 8) & 1u)) w[2] = 0.f;
                if (!((mb >> 9) & 1u)) w[3] = 0.f;
                zacc[i] += (w[0] + w[1]) + (w[2] + w[3]);
                __nv_bfloat162 h01 = __floats2bfloat162_rn(w[0], w[1]);
                __nv_bfloat162 h23 = __floats2bfloat162_rn(w[2], w[3]);
                float l0 = w[0] - __low2float(h01), l1 = w[1] - __high2float(h01);
                float l2 = w[2] - __low2float(h23), l3 = w[3] - __high2float(h23);
                __nv_bfloat162 L01 = __floats2bfloat162_rn(l0, l1);
                __nv_bfloat162 L23 = __floats2bfloat162_rn(l2, l3);
                aH[Mt][rh]     = *(uint32_t*)&h01;
                aH[Mt][2 + rh] = *(uint32_t*)&h23;
                aL[Mt][rh]     = *(uint32_t*)&L01;
                aL[Mt][2 + rh] = *(uint32_t*)&L23;
            }
#pragma unroll
            for (int nt2 = 0; nt2 < NTN / 2; nt2++) {
                int drow = Ng * NCOLW + nt2 * 16 + (g2 >> 1) * 8 + rin;
                int colb = kt * 16 + (g2 & 1) * 8;
                uint32_t off = (uint32_t)(((buf * D + drow) * 72 + colb) * 2);
                uint32_t bh[4], bl[4];
                LDSM4(bh, sb + off);
                LDSM4(bl, sb + O_BL + off);
#pragma unroll
                for (int Mt = 0; Mt < 2; Mt++) {
                    mma_bf16(acc[Mt][2 * nt2],     aH[Mt][0], aH[Mt][1], aH[Mt][2], aH[Mt][3], bh[0], bh[1]);
                    mma_bf16(acc[Mt][2 * nt2 + 1], aH[Mt][0], aH[Mt][1], aH[Mt][2], aH[Mt][3], bh[2], bh[3]);
                    mma_bf16(acc[Mt][2 * nt2],     aH[Mt][0], aH[Mt][1], aH[Mt][2], aH[Mt][3], bl[0], bl[1]);
                    mma_bf16(acc[Mt][2 * nt2 + 1], aH[Mt][0], aH[Mt][1], aH[Mt][2], aH[Mt][3], bl[2], bl[3]);
                    mma_bf16(acc[Mt][2 * nt2],     aL[Mt][0], aL[Mt][1], aL[Mt][2], aL[Mt][3], bh[0], bh[1]);
                    mma_bf16(acc[Mt][2 * nt2 + 1], aL[Mt][0], aL[Mt][1], aL[Mt][2], aL[Mt][3], bh[2], bh[3]);
                }
            }
        }
#pragma unroll
        for (int i = 0; i < 4; i++) amask[i] = amaskN[i];
        __syncthreads();
    }

    // Z (quad reduce; rows are per lane-quad)
#pragma unroll
    for (int i = 0; i < 4; i++) {
        float z = zacc[i];
        z += __shfl_xor_sync(~0u, z, 1);
        z += __shfl_xor_sync(~0u, z, 2);
        if (Ng == 0 && (lane & 3) == 0)
            Zs[Mg * 32 + rq + (i & 1) * 8 + (i >> 1) * 16] = 1.f / z;
    }
    __syncthreads();

    float* out = (D == 128) ? g_cat1 : g_cat2;
    const int ostr = (D == 128) ? 512 : 256;
#pragma unroll
    for (int Mt = 0; Mt < 2; Mt++) {
        int r0 = Mg * 32 + Mt * 16 + rq;
        float zi0 = Zs[r0], zi1 = Zs[r0 + 8];
#pragma unroll
        for (int Nt = 0; Nt < NTN; Nt++) {
            int col = Ng * NCOLW + Nt * 8 + (lane & 3) * 2;
            float v0 = acc[Mt][Nt][0] * zi0, v1 = acc[Mt][Nt][1] * zi0;
            float v2 = acc[Mt][Nt][2] * zi1, v3 = acc[Mt][Nt][3] * zi1;
            if (D == 128) {
                float2 ra = *(const float2*)&resid[(size_t)(n0 + r0) * 128 + col];
                float2 rb = *(const float2*)&resid[(size_t)(n0 + r0 + 8) * 128 + col];
                v0 += ra.x; v1 += ra.y; v2 += rb.x; v3 += rb.y;
            }
            float2 o0 = {eluf(v0), eluf(v1)};
            float2 o1 = {eluf(v2), eluf(v3)};
            *(float2*)&out[(size_t)(n0 + r0) * ostr + head * D + col]     = o0;
            *(float2*)&out[(size_t)(n0 + r0 + 8) * ostr + head * D + col] = o1;
        }
    }
}

// ---------------- SIMT agg for layer 3 (D=16) ----------------
__device__ __forceinline__ ull dupf(float v) {
    ull r; asm("mov.b64 %0, {%1, %1};" : "=l"(r) : "f"(v)); return r;
}
__device__ __forceinline__ void ffma2(ull& acc, ull a, ull b) {
    asm("fma.rn.f32x2 %0, %1, %2, %0;" : "+l"(acc) : "l"(a), "l"(b));
}
__device__ __forceinline__ float2 unpack2(ull v) {
    float2 r; asm("mov.b64 {%0, %1}, %2;" : "=f"(r.x), "=f"(r.y) : "l"(v)); return r;
}

__global__ __launch_bounds__(128) void agg3_k() {
    const int D = 16, TN = 32, TM = 32, MR = 2, NC = 2;
    __shared__ __align__(16) float hs[2][TM][D];
    __shared__ __align__(16) float ws[2][TM][TN + 2];
    __shared__ float Zred[128];
    __shared__ float Zs[TN];

    const int t  = threadIdx.x;
    const int n0 = blockIdx.x * TN;
    const float* hfh = g_hf;

    const int rA = t % TN;
    const int G  = 128 / TN;
    const int g  = t / TN;
    const int MMPT = TM / G;

    const float rf1  = g_f1[n0 + rA];
    const float rE1  = g_E1[n0 + rA];
    const float rE1s = g_E1s[n0 + rA];
    float zacc = 0.f;

    const int rg = t / (D / NC);
    const int cg = t % (D / NC);

    ull acc[NC];
#pragma unroll
    for (int j = 0; j < NC; j++) acc[j] = 0ull;

    auto fill = [&](int wti, int buf) {
        int m0 = wti * TM;
        for (int idx = t; idx < TM * (D / 4); idx += 128) {
            int m  = idx / (D / 4);
            int dd = idx % (D / 4);
            *(float4*)&hs[buf][m][4 * dd] = *(const float4*)&hfh[(size_t)(m0 + m) * D + 4 * dd];
        }
        unsigned aw = g_adjbits[(size_t)(n0 + rA) * NW + wti];
#pragma unroll
        for (int j = 0; j < MMPT; j++) {
            int mm = g + G * j;
            float w = 0.f;
            if ((aw >> mm) & 1u) {
                float s = rf1 + g_f2[m0 + mm];
                w = (s >= 0.f) ? rE1 * g_E2[m0 + mm] : rE1s * g_E2s[m0 + mm];
            }
            ws[buf][mm][rA] = w;
            zacc += w;
        }
    };

    fill(0, 0);
    __syncthreads();
    const int NT = NNODES / TM;
    for (int mt = 0; mt < NT; mt++) {
        int cur = mt & 1;
        if (mt + 1 < NT) fill(mt + 1, cur ^ 1);
#pragma unroll
        for (int k = 0; k < TM; k++) {
            ull a2 = *(const ull*)&ws[cur][k][rg * MR];
#pragma unroll
            for (int j = 0; j < NC; j++) {
                ull bb = dupf(hs[cur][k][cg * NC + j]);
                ffma2(acc[j], a2, bb);
            }
        }
        __syncthreads();
    }
    Zred[t] = zacc;
    __syncthreads();
    if (t < TN) {
        float z = 0.f;
#pragma unroll
        for (int q = 0; q < G; q++) z += Zred[t + q * TN];
        Zs[t] = 1.f / z;
    }
    __syncthreads();
    {
        int lr0 = rg * MR;
        float zi0 = Zs[lr0], zi1 = Zs[lr0 + 1];
#pragma unroll
        for (int j = 0; j < NC; j++) {
            float2 v = unpack2(acc[j]);
            int d = cg * NC + j;
            g_h3[(size_t)(n0 + lr0) * 16 + d]     = eluf(v.x * zi0);
            g_h3[(size_t)(n0 + lr0 + 1) * 16 + d] = eluf(v.y * zi1);
        }
    }
}

// ---------------- final log-softmax ----------------
__global__ __launch_bounds__(256) void logsoftmax_k(float* __restrict__ out) {
    int n    = blockIdx.x * 8 + (threadIdx.x >> 5);
    int lane = threadIdx.x & 31;
    if (n >= NNODES) return;
    float v = (lane < 16) ? g_h3[n * 16 + lane] : -INFINITY;
    float m = v;
#pragma unroll
    for (int o = 16; o; o >>= 1) m = fmaxf(m, __shfl_xor_sync(~0u, m, o));
    float e = (lane < 16) ? expf(v - m) : 0.f;
    float s = e;
#pragma unroll
    for (int o = 16; o; o >>= 1) s += __shfl_xor_sync(~0u, s, o);
    if (lane < 16) out[n * 16 + lane] = v - m - logf(s);
}

// ---------------- launch ----------------
extern "C" void kernel_launch(void* const* d_in, const int* in_sizes, int n_in,
                              void* d_out, int out_size) {
    const float* x     = (const float*)d_in[0];
    const int*   adj   = (const int*)d_in[1];
    const float* W_in  = (const float*)d_in[2];
    const float* a_in  = (const float*)d_in[3];
    const float* W_hid = (const float*)d_in[4];
    const float* a_hid = (const float*)d_in[5];
    const float* W_out = (const float*)d_in[6];
    const float* a_out = (const float*)d_in[7];
    float* out = (float*)d_out;

    const int SMEM_L1 = 2 * 128 * 288 + 2048;   // 75776
    const int SMEM_L2 = 2 * 64 * 288 + 2048;    // 38912
    cudaFuncSetAttribute(aggM_k<128>, cudaFuncAttributeMaxDynamicSharedMemorySize, SMEM_L1);
    cudaFuncSetAttribute(aggM_k<64>,  cudaFuncAttributeMaxDynamicSharedMemorySize, SMEM_L2);

    pack_adj<<<(NNODES * NW + 255) / 256, 256>>>(adj);

    // Layer 1
    gemm_k<64, 64, 4, 4, 0><<<dim3(64, 2, 4), 256>>>(x, W_in, 128, 128);
    scores_k<<<(NHEADS * NNODES) / 8, 256>>>(a_in, 128, NHEADS * NNODES);
    transpose_split_k<128><<<dim3(128, 4, 4), 256>>>();
    aggM_k<128><<<dim3(32, 4), 256, SMEM_L1>>>(x);

    // Layer 2
    gemm_k<64, 64, 4, 4, 1><<<dim3(64, 1, 4), 256>>>(nullptr, W_hid, 512, 64);
    scores_k<<<(NHEADS * NNODES) / 8, 256>>>(a_hid, 64, NHEADS * NNODES);
    transpose_split_k<64><<<dim3(128, 2, 4), 256>>>();
    aggM_k<64><<<dim3(32, 4), 256, SMEM_L2>>>(nullptr);

    // Layer 3
    gemm_k<64, 16, 4, 1, 2><<<dim3(64, 1, 1), 256>>>(nullptr, W_out, 256, 16);
    scores_k<<<NNODES / 8, 256>>>(a_out, 16, NNODES);
    agg3_k<<<dim3(128, 1, 1), 128>>>();

    logsoftmax_k<<<NNODES / 8, 256>>>(out);
}

// round 6
// speedup vs baseline: 2.2248x; 1.3893x over previous
#include <cuda_runtime.h>
#include <cuda_bf16.h>
#include <cstdint>
#include <math.h>

#define NNODES 4096
#define NW 128
#define NHEADS 4

typedef unsigned long long ull;

// ---------------- scratch ----------------
__device__ unsigned g_adjbits[NNODES * NW];
__device__ float g_hf[NHEADS * NNODES * 128];
__device__ float g_f1[NHEADS * NNODES];
__device__ float g_f2[NHEADS * NNODES];
__device__ float g_E1[NHEADS * NNODES];
__device__ float g_E1s[NHEADS * NNODES];
__device__ float g_E2[NHEADS * NNODES];
__device__ float g_E2s[NHEADS * NNODES];
__device__ float g_cat1[NNODES * 512];
__device__ float g_cat2[NNODES * 256];
__device__ float g_h3[NNODES * 16];
__device__ __nv_bfloat16 g_hTb_hi[NHEADS * 128 * NNODES];   // [h][d][m]
__device__ __nv_bfloat16 g_hTb_lo[NHEADS * 128 * NNODES];

__device__ __forceinline__ float eluf(float v) { return v > 0.f ? v : expm1f(v); }

__device__ __forceinline__ uint32_t smem_u32(const void* p) {
    uint32_t a;
    asm("{ .reg .u64 t; cvta.to.shared.u64 t, %1; cvt.u32.u64 %0, t; }" : "=r"(a) : "l"(p));
    return a;
}

#define CP16(dst, src) \
    asm volatile("cp.async.cg.shared.global [%0], [%1], 16;" :: "r"(dst), "l"(src))
#define CP_COMMIT() asm volatile("cp.async.commit_group;" ::: "memory")
#define CP_WAIT(n)  asm volatile("cp.async.wait_group %0;" :: "n"(n) : "memory")

#define LDSM4(r, a)                                                            \
    asm volatile("ldmatrix.sync.aligned.m8n8.x4.shared.b16 {%0,%1,%2,%3}, [%4];" \
        : "=r"((r)[0]), "=r"((r)[1]), "=r"((r)[2]), "=r"((r)[3]) : "r"(a))

__device__ __forceinline__ void mma_bf16(float* c, uint32_t a0, uint32_t a1,
                                         uint32_t a2, uint32_t a3,
                                         uint32_t b0, uint32_t b1) {
    asm volatile(
        "mma.sync.aligned.m16n8k16.row.col.f32.bf16.bf16.f32 "
        "{%0,%1,%2,%3}, {%4,%5,%6,%7}, {%8,%9}, {%0,%1,%2,%3};"
        : "+f"(c[0]), "+f"(c[1]), "+f"(c[2]), "+f"(c[3])
        : "r"(a0), "r"(a1), "r"(a2), "r"(a3), "r"(b0), "r"(b1));
}

// ---------------- adjacency bit-pack ----------------
__global__ void pack_adj(const int* __restrict__ adj) {
    int wi = blockIdx.x * blockDim.x + threadIdx.x;
    if (wi >= NNODES * NW) return;
    const int4* p = (const int4*)adj + (size_t)wi * 8;
    unsigned w = 0;
#pragma unroll
    for (int q = 0; q < 8; q++) {
        int4 v = p[q];
        if (v.x > 0) w |= 1u << (q * 4 + 0);
        if (v.y > 0) w |= 1u << (q * 4 + 1);
        if (v.z > 0) w |= 1u << (q * 4 + 2);
        if (v.w > 0) w |= 1u << (q * 4 + 3);
    }
    g_adjbits[wi] = w;
}

// ---------------- feature GEMM ----------------
template<int TN, int TD, int MR, int NC, int SRC>
__global__ __launch_bounds__(256) void gemm_k(const float* __restrict__ Aext,
                                              const float* __restrict__ W,
                                              int K, int Dtot) {
    const int TK = 16;
    __shared__ float As[TK][TN];
    __shared__ float Bs[TK][TD];
    const float* A = (SRC == 0) ? Aext : (SRC == 1 ? g_cat1 : g_cat2);

    int t = threadIdx.x;
    int n0 = blockIdx.x * TN;
    int d0 = blockIdx.y * TD;
    int h  = blockIdx.z;
    const float* Wh = W + (size_t)h * K * Dtot;
    const int rg = t / (TD / NC);
    const int cg = t % (TD / NC);

    float acc[MR][NC];
#pragma unroll
    for (int i = 0; i < MR; i++)
#pragma unroll
        for (int j = 0; j < NC; j++) acc[i][j] = 0.f;

    for (int k0 = 0; k0 < K; k0 += TK) {
        for (int idx = t; idx < TN * (TK / 4); idx += 256) {
            int i_n = idx / (TK / 4);
            int k4  = idx % (TK / 4);
            float4 v = *(const float4*)&A[(size_t)(n0 + i_n) * K + k0 + 4 * k4];
            As[4 * k4 + 0][i_n] = v.x;
            As[4 * k4 + 1][i_n] = v.y;
            As[4 * k4 + 2][i_n] = v.z;
            As[4 * k4 + 3][i_n] = v.w;
        }
        for (int idx = t; idx < TK * (TD / 4); idx += 256) {
            int kk = idx / (TD / 4);
            int j4 = idx % (TD / 4);
            *(float4*)&Bs[kk][4 * j4] =
                *(const float4*)&Wh[(size_t)(k0 + kk) * Dtot + d0 + 4 * j4];
        }
        __syncthreads();
#pragma unroll
        for (int k = 0; k < TK; k++) {
            float a_[MR], b_[NC];
#pragma unroll
            for (int i = 0; i < MR; i++) a_[i] = As[k][rg * MR + i];
#pragma unroll
            for (int j = 0; j < NC; j++) b_[j] = Bs[k][cg * NC + j];
#pragma unroll
            for (int i = 0; i < MR; i++)
#pragma unroll
                for (int j = 0; j < NC; j++)
                    acc[i][j] = fmaf(a_[i], b_[j], acc[i][j]);
        }
        __syncthreads();
    }
    float* Ch = g_hf + (size_t)h * NNODES * Dtot;
#pragma unroll
    for (int i = 0; i < MR; i++)
#pragma unroll
        for (int j = 0; j < NC; j++)
            Ch[(size_t)(n0 + rg * MR + i) * Dtot + d0 + cg * NC + j] = acc[i][j];
}

// ---------------- scores ----------------
__global__ __launch_bounds__(256) void scores_k(const float* __restrict__ a, int D, int total) {
    int gid  = blockIdx.x * 8 + (threadIdx.x >> 5);
    int lane = threadIdx.x & 31;
    if (gid >= total) return;
    int h = gid / NNODES, n = gid % NNODES;
    const float* hr = g_hf + ((size_t)h * NNODES + n) * D;
    const float* a1 = a + (size_t)h * 2 * D;
    const float* a2 = a1 + D;
    float s1 = 0.f, s2 = 0.f;
    for (int d = lane; d < D; d += 32) {
        float v = hr[d];
        s1 += v * a1[d];
        s2 += v * a2[d];
    }
#pragma unroll
    for (int o = 16; o; o >>= 1) {
        s1 += __shfl_xor_sync(~0u, s1, o);
        s2 += __shfl_xor_sync(~0u, s2, o);
    }
    if (!lane) {
        int idx = h * NNODES + n;
        g_f1[idx]  = s1;
        g_f2[idx]  = s2;
        g_E1[idx]  = expf(s1);
        g_E1s[idx] = expf(0.2f * s1);
        g_E2[idx]  = expf(s2);
        g_E2s[idx] = expf(0.2f * s2);
    }
}

// ---------------- transpose + bf16 split: g_hf[h][n][d] -> g_hTb_{hi,lo}[h][d][n] ----------------
template<int D>
__global__ __launch_bounds__(256) void transpose_split_k() {
    __shared__ float ts[32][33];
    int t  = threadIdx.x;
    int nt = blockIdx.x, dt = blockIdx.y, h = blockIdx.z;
    int r0 = t / 32, c = t % 32;
#pragma unroll
    for (int p = 0; p < 4; p++) {
        int r = p * 8 + r0;
        ts[r][c] = g_hf[((size_t)h * NNODES + nt * 32 + r) * D + dt * 32 + c];
    }
    __syncthreads();
#pragma unroll
    for (int p = 0; p < 4; p++) {
        int dr = p * 8 + r0;
        float v = ts[c][dr];
        __nv_bfloat16 hi = __float2bfloat16(v);
        float lo = v - __bfloat162float(hi);
        size_t addr = ((size_t)h * D + dt * 32 + dr) * NNODES + nt * 32 + c;
        g_hTb_hi[addr] = hi;
        g_hTb_lo[addr] = __float2bfloat16(lo);
    }
}

// ---------------- mma.sync masked-softmax aggregation v2 ----------------
// CTA: 32 n-rows x 64 d-cols. 128 threads = 4 warps (2 Mg x 2 Ng).
// blockIdx = (n-tile, head, d-half). 3-stage cp.async ring, chunk = 64 m.
// smem: 3 bufs x (Bhi 8K + Blo 8K) + 3 x (f2,E2,E2s)[64] + Zs[32]
template<int D>
__global__ __launch_bounds__(128, 4) void aggM_k(const float* __restrict__ resid) {
    constexpr int NCH = NNODES / 64;
    const int O_E  = 49152;
    const int O_ZS = 51456;

    extern __shared__ __align__(16) char sm[];
    const uint32_t sb = smem_u32(sm);
    float* Zs = (float*)(sm + O_ZS);

    const int t = threadIdx.x, lane = t & 31, wid = t >> 5;
    const int Mg = wid >> 1, Ng = wid & 1;
    const int n0 = blockIdx.x * 32;
    const int head = blockIdx.y;
    const int dc0 = blockIdx.z * 64;
    const int headN = head * NNODES;
    const int rq = lane >> 2;
    const int k0 = (lane & 3) * 2;
    const int g2 = lane >> 3, rin = lane & 7;

    // row constants: 2 rows per thread (rq, rq+8) within Mg's 16-row tile
    float f1r[2], E1r[2], E1sr[2];
    const unsigned* adjrow[2];
#pragma unroll
    for (int i = 0; i < 2; i++) {
        int r = Mg * 16 + rq + i * 8;
        f1r[i]  = g_f1[headN + n0 + r];
        E1r[i]  = g_E1[headN + n0 + r];
        E1sr[i] = g_E1s[headN + n0 + r];
        adjrow[i] = &g_adjbits[(size_t)(n0 + r) * NW];
    }

    float acc[4][4];
#pragma unroll
    for (int a = 0; a < 4; a++)
#pragma unroll
        for (int q = 0; q < 4; q++) acc[a][q] = 0.f;
    float zacc[2] = {0.f, 0.f};

    auto fill = [&](int chunk, int buf) {
        // B tiles: 64 d-rows x 64 m, 128B rows, XOR swizzle, hi at +0, lo at +8192
        for (int idx = t; idx < 512; idx += 128) {
            int row = idx >> 3, c8 = idx & 7;
            uint32_t dst = sb + (uint32_t)(buf * 16384 + row * 128 +
                                           ((c8 * 16) ^ ((row & 7) << 4)));
            size_t s = ((size_t)(head * D + dc0 + row)) * NNODES + chunk * 64 + c8 * 8;
            CP16(dst, (const void*)(g_hTb_hi + s));
            CP16(dst + 8192, (const void*)(g_hTb_lo + s));
        }
        if (t < 48) {
            int a = t >> 4, q = t & 15;
            const float* s = (a == 0 ? g_f2 : a == 1 ? g_E2 : g_E2s) +
                             headN + chunk * 64 + q * 4;
            uint32_t dst = sb + (uint32_t)(O_E + buf * 768 + a * 256 + q * 16);
            CP16(dst, (const void*)s);
        }
    };

    ull amask[2], amaskN[2];
#pragma unroll
    for (int i = 0; i < 2; i++) { amask[i] = *(const ull*)(adjrow[i]); amaskN[i] = amask[i]; }

    fill(0, 0); CP_COMMIT();
    fill(1, 1); CP_COMMIT();

    for (int c = 0; c < NCH; c++) {
        const int buf = c % 3;
        if (c == NCH - 1) CP_WAIT(0); else CP_WAIT(1);
        __syncthreads();
        if (c + 1 < NCH) {
#pragma unroll
            for (int i = 0; i < 2; i++)
                amaskN[i] = *(const ull*)(adjrow[i] + 2 * (c + 1));
        }
        const uint32_t Bb = sb + (uint32_t)(buf * 16384);
        const float* f2c  = (const float*)(sm + O_E + buf * 768);
        const float* E2c  = f2c + 64;
        const float* E2sc = f2c + 128;

#pragma unroll
        for (int kt = 0; kt < 4; kt++) {
            float f2v[4], e2v[4], e2sv[4];
#pragma unroll
            for (int q = 0; q < 4; q++) {
                int mloc = kt * 16 + (q >> 1) * 8 + k0 + (q & 1);
                f2v[q] = f2c[mloc]; e2v[q] = E2c[mloc]; e2sv[q] = E2sc[mloc];
            }
            uint32_t aH[4], aL[4];
#pragma unroll
            for (int i = 0; i < 2; i++) {
                float w[4];
#pragma unroll
                for (int q = 0; q < 4; q++) {
                    float s = f1r[i] + f2v[q];
                    w[q] = (s >= 0.f) ? E1r[i] * e2v[q] : E1sr[i] * e2sv[q];
                }
                unsigned mb = (unsigned)(amask[i] >> (kt * 16 + k0));
                if (!(mb & 1u)) w[0] = 0.f;
                if (!(mb & 2u)) w[1] = 0.f;
                if (!((mb >> 8) & 1u)) w[2] = 0.f;
                if (!((mb >> 9) & 1u)) w[3] = 0.f;
                zacc[i] += (w[0] + w[1]) + (w[2] + w[3]);
                __nv_bfloat162 h01 = __floats2bfloat162_rn(w[0], w[1]);
                __nv_bfloat162 h23 = __floats2bfloat162_rn(w[2], w[3]);
                float l0 = w[0] - __low2float(h01), l1 = w[1] - __high2float(h01);
                float l2 = w[2] - __low2float(h23), l3 = w[3] - __high2float(h23);
                __nv_bfloat162 L01 = __floats2bfloat162_rn(l0, l1);
                __nv_bfloat162 L23 = __floats2bfloat162_rn(l2, l3);
                aH[i]     = *(uint32_t*)&h01;
                aH[2 + i] = *(uint32_t*)&h23;
                aL[i]     = *(uint32_t*)&L01;
                aL[2 + i] = *(uint32_t*)&L23;
            }
#pragma unroll
            for (int nt2 = 0; nt2 < 2; nt2++) {
                int drow = Ng * 32 + nt2 * 16 + (g2 >> 1) * 8 + rin;
                uint32_t cb = (uint32_t)((kt * 16 + (g2 & 1) * 8) * 2);
                uint32_t addr = Bb + (uint32_t)(drow * 128) + (cb ^ ((uint32_t)(drow & 7) << 4));
                uint32_t bh[4], bl[4];
                LDSM4(bh, addr);
                LDSM4(bl, addr + 8192);
                mma_bf16(acc[2 * nt2],     aH[0], aH[1], aH[2], aH[3], bh[0], bh[1]);
                mma_bf16(acc[2 * nt2 + 1], aH[0], aH[1], aH[2], aH[3], bh[2], bh[3]);
                mma_bf16(acc[2 * nt2],     aH[0], aH[1], aH[2], aH[3], bl[0], bl[1]);
                mma_bf16(acc[2 * nt2 + 1], aH[0], aH[1], aH[2], aH[3], bl[2], bl[3]);
                mma_bf16(acc[2 * nt2],     aL[0], aL[1], aL[2], aL[3], bh[0], bh[1]);
                mma_bf16(acc[2 * nt2 + 1], aL[0], aL[1], aL[2], aL[3], bh[2], bh[3]);
            }
        }
#pragma unroll
        for (int i = 0; i < 2; i++) amask[i] = amaskN[i];
        if (c + 2 < NCH) { fill(c + 2, (c + 2) % 3); CP_COMMIT(); }
    }

    // Z reduce over lane quads (m partials); rows owned by lane quads
#pragma unroll
    for (int i = 0; i < 2; i++) {
        float z = zacc[i];
        z += __shfl_xor_sync(~0u, z, 1);
        z += __shfl_xor_sync(~0u, z, 2);
        if (Ng == 0 && (lane & 3) == 0) Zs[Mg * 16 + rq + i * 8] = 1.f / z;
    }
    __syncthreads();

    float* out = (D == 128) ? g_cat1 : g_cat2;
    const int ostr = (D == 128) ? 512 : 256;
#pragma unroll
    for (int i = 0; i < 2; i++) {
        int lr = Mg * 16 + rq + i * 8;
        int n  = n0 + lr;
        float zi = Zs[lr];
#pragma unroll
        for (int nt = 0; nt < 4; nt++) {
            int col = Ng * 32 + nt * 8 + (lane & 3) * 2;
            float v0 = acc[nt][2 * i]     * zi;
            float v1 = acc[nt][2 * i + 1] * zi;
            if (D == 128) {
                float2 rx = *(const float2*)&resid[(size_t)n * 128 + dc0 + col];
                v0 += rx.x; v1 += rx.y;
            }
            float2 o = {eluf(v0), eluf(v1)};
            *(float2*)&out[(size_t)n * ostr + head * D + dc0 + col] = o;
        }
    }
}

// ---------------- SIMT agg for layer 3 (D=16) ----------------
__device__ __forceinline__ ull dupf(float v) {
    ull r; asm("mov.b64 %0, {%1, %1};" : "=l"(r) : "f"(v)); return r;
}
__device__ __forceinline__ void ffma2(ull& acc, ull a, ull b) {
    asm("fma.rn.f32x2 %0, %1, %2, %0;" : "+l"(acc) : "l"(a), "l"(b));
}
__device__ __forceinline__ float2 unpack2(ull v) {
    float2 r; asm("mov.b64 {%0, %1}, %2;" : "=f"(r.x), "=f"(r.y) : "l"(v)); return r;
}

__global__ __launch_bounds__(128) void agg3_k() {
    const int D = 16, TN = 32, TM = 32, MR = 2, NC = 2;
    __shared__ __align__(16) float hs[2][TM][D];
    __shared__ __align__(16) float ws[2][TM][TN + 2];
    __shared__ float Zred[128];
    __shared__ float Zs[TN];

    const int t  = threadIdx.x;
    const int n0 = blockIdx.x * TN;
    const float* hfh = g_hf;

    const int rA = t % TN;
    const int G  = 128 / TN;
    const int g  = t / TN;
    const int MMPT = TM / G;

    const float rf1  = g_f1[n0 + rA];
    const float rE1  = g_E1[n0 + rA];
    const float rE1s = g_E1s[n0 + rA];
    float zacc = 0.f;

    const int rg = t / (D / NC);
    const int cg = t % (D / NC);

    ull acc[NC];
#pragma unroll
    for (int j = 0; j < NC; j++) acc[j] = 0ull;

    auto fill = [&](int wti, int buf) {
        int m0 = wti * TM;
        for (int idx = t; idx < TM * (D / 4); idx += 128) {
            int m  = idx / (D / 4);
            int dd = idx % (D / 4);
            *(float4*)&hs[buf][m][4 * dd] = *(const float4*)&hfh[(size_t)(m0 + m) * D + 4 * dd];
        }
        unsigned aw = g_adjbits[(size_t)(n0 + rA) * NW + wti];
#pragma unroll
        for (int j = 0; j < MMPT; j++) {
            int mm = g + G * j;
            float w = 0.f;
            if ((aw >> mm) & 1u) {
                float s = rf1 + g_f2[m0 + mm];
                w = (s >= 0.f) ? rE1 * g_E2[m0 + mm] : rE1s * g_E2s[m0 + mm];
            }
            ws[buf][mm][rA] = w;
            zacc += w;
        }
    };

    fill(0, 0);
    __syncthreads();
    const int NT = NNODES / TM;
    for (int mt = 0; mt < NT; mt++) {
        int cur = mt & 1;
        if (mt + 1 < NT) fill(mt + 1, cur ^ 1);
#pragma unroll
        for (int k = 0; k < TM; k++) {
            ull a2 = *(const ull*)&ws[cur][k][rg * MR];
#pragma unroll
            for (int j = 0; j < NC; j++) {
                ull bb = dupf(hs[cur][k][cg * NC + j]);
                ffma2(acc[j], a2, bb);
            }
        }
        __syncthreads();
    }
    Zred[t] = zacc;
    __syncthreads();
    if (t < TN) {
        float z = 0.f;
#pragma unroll
        for (int q = 0; q < G; q++) z += Zred[t + q * TN];
        Zs[t] = 1.f / z;
    }
    __syncthreads();
    {
        int lr0 = rg * MR;
        float zi0 = Zs[lr0], zi1 = Zs[lr0 + 1];
#pragma unroll
        for (int j = 0; j < NC; j++) {
            float2 v = unpack2(acc[j]);
            int d = cg * NC + j;
            g_h3[(size_t)(n0 + lr0) * 16 + d]     = eluf(v.x * zi0);
            g_h3[(size_t)(n0 + lr0 + 1) * 16 + d] = eluf(v.y * zi1);
        }
    }
}

// ---------------- final log-softmax ----------------
__global__ __launch_bounds__(256) void logsoftmax_k(float* __restrict__ out) {
    int n    = blockIdx.x * 8 + (threadIdx.x >> 5);
    int lane = threadIdx.x & 31;
    if (n >= NNODES) return;
    float v = (lane < 16) ? g_h3[n * 16 + lane] : -INFINITY;
    float m = v;
#pragma unroll
    for (int o = 16; o; o >>= 1) m = fmaxf(m, __shfl_xor_sync(~0u, m, o));
    float e = (lane < 16) ? expf(v - m) : 0.f;
    float s = e;
#pragma unroll
    for (int o = 16; o; o >>= 1) s += __shfl_xor_sync(~0u, s, o);
    if (lane < 16) out[n * 16 + lane] = v - m - logf(s);
}

// ---------------- launch ----------------
extern "C" void kernel_launch(void* const* d_in, const int* in_sizes, int n_in,
                              void* d_out, int out_size) {
    const float* x     = (const float*)d_in[0];
    const int*   adj   = (const int*)d_in[1];
    const float* W_in  = (const float*)d_in[2];
    const float* a_in  = (const float*)d_in[3];
    const float* W_hid = (const float*)d_in[4];
    const float* a_hid = (const float*)d_in[5];
    const float* W_out = (const float*)d_in[6];
    const float* a_out = (const float*)d_in[7];
    float* out = (float*)d_out;

    const int SMEM_AGG = 51456 + 128 + 16;   // B ring 48K + E ring + Zs
    cudaFuncSetAttribute(aggM_k<128>, cudaFuncAttributeMaxDynamicSharedMemorySize, SMEM_AGG);
    cudaFuncSetAttribute(aggM_k<64>,  cudaFuncAttributeMaxDynamicSharedMemorySize, SMEM_AGG);

    pack_adj<<<(NNODES * NW + 255) / 256, 256>>>(adj);

    // Layer 1
    gemm_k<64, 64, 4, 4, 0><<<dim3(64, 2, 4), 256>>>(x, W_in, 128, 128);
    scores_k<<<(NHEADS * NNODES) / 8, 256>>>(a_in, 128, NHEADS * NNODES);
    transpose_split_k<128><<<dim3(128, 4, 4), 256>>>();
    aggM_k<128><<<dim3(128, 4, 2), 128, SMEM_AGG>>>(x);

    // Layer 2
    gemm_k<64, 64, 4, 4, 1><<<dim3(64, 1, 4), 256>>>(nullptr, W_hid, 512, 64);
    scores_k<<<(NHEADS * NNODES) / 8, 256>>>(a_hid, 64, NHEADS * NNODES);
    transpose_split_k<64><<<dim3(128, 2, 4), 256>>>();
    aggM_k<64><<<dim3(128, 4, 1), 128, SMEM_AGG>>>(nullptr);

    // Layer 3
    gemm_k<64, 16, 4, 1, 2><<<dim3(64, 1, 1), 256>>>(nullptr, W_out, 256, 16);
    scores_k<<<NNODES / 8, 256>>>(a_out, 16, NNODES);
    agg3_k<<<dim3(128, 1, 1), 128>>>();

    logsoftmax_k<<<NNODES / 8, 256>>>(out);
}

// round 7
// speedup vs baseline: 2.2721x; 1.0212x over previous
#include <cuda_runtime.h>
#include <cuda_bf16.h>
#include <cstdint>
#include <math.h>

#define NNODES 4096
#define NW 128
#define NHEADS 4

typedef unsigned long long ull;

// ---------------- scratch ----------------
__device__ unsigned g_adjbits[NNODES * NW];
__device__ float g_hf[NHEADS * NNODES * 128];
__device__ float g_f1[NHEADS * NNODES];
__device__ float g_f2[NHEADS * NNODES];
__device__ float g_E1[NHEADS * NNODES];
__device__ float g_E1s[NHEADS * NNODES];
__device__ float g_E2[NHEADS * NNODES];
__device__ float g_E2s[NHEADS * NNODES];
__device__ float g_cat1[NNODES * 512];
__device__ float g_cat2[NNODES * 256];
__device__ float g_h3[NNODES * 16];
__device__ float g_hT[NHEADS * 128 * NNODES];    // [h][d][m], tf32-rounded fp32

__device__ __forceinline__ float eluf(float v) { return v > 0.f ? v : expm1f(v); }

__device__ __forceinline__ uint32_t smem_u32(const void* p) {
    uint32_t a;
    asm("{ .reg .u64 t; cvta.to.shared.u64 t, %1; cvt.u32.u64 %0, t; }" : "=r"(a) : "l"(p));
    return a;
}
__device__ __forceinline__ uint32_t tf32u(float v) {
    uint32_t r;
    asm("cvt.rna.tf32.f32 %0, %1;" : "=r"(r) : "f"(v));
    return r;
}

#define CP16(dst, src) \
    asm volatile("cp.async.cg.shared.global [%0], [%1], 16;" :: "r"(dst), "l"(src))
#define CP_COMMIT() asm volatile("cp.async.commit_group;" ::: "memory")
#define CP_WAIT(n)  asm volatile("cp.async.wait_group %0;" :: "n"(n) : "memory")

__device__ __forceinline__ void mma_tf32(float* c, uint32_t a0, uint32_t a1,
                                         uint32_t a2, uint32_t a3,
                                         uint32_t b0, uint32_t b1) {
    asm volatile(
        "mma.sync.aligned.m16n8k8.row.col.f32.tf32.tf32.f32 "
        "{%0,%1,%2,%3}, {%4,%5,%6,%7}, {%8,%9}, {%0,%1,%2,%3};"
        : "+f"(c[0]), "+f"(c[1]), "+f"(c[2]), "+f"(c[3])
        : "r"(a0), "r"(a1), "r"(a2), "r"(a3), "r"(b0), "r"(b1));
}

// ---------------- adjacency bit-pack ----------------
__global__ void pack_adj(const int* __restrict__ adj) {
    int wi = blockIdx.x * blockDim.x + threadIdx.x;
    if (wi >= NNODES * NW) return;
    const int4* p = (const int4*)adj + (size_t)wi * 8;
    unsigned w = 0;
#pragma unroll
    for (int q = 0; q < 8; q++) {
        int4 v = p[q];
        if (v.x > 0) w |= 1u << (q * 4 + 0);
        if (v.y > 0) w |= 1u << (q * 4 + 1);
        if (v.z > 0) w |= 1u << (q * 4 + 2);
        if (v.w > 0) w |= 1u << (q * 4 + 3);
    }
    g_adjbits[wi] = w;
}

// ---------------- feature GEMM ----------------
template<int TN, int TD, int MR, int NC, int SRC>
__global__ __launch_bounds__(256) void gemm_k(const float* __restrict__ Aext,
                                              const float* __restrict__ W,
                                              int K, int Dtot) {
    const int TK = 16;
    __shared__ float As[TK][TN];
    __shared__ float Bs[TK][TD];
    const float* A = (SRC == 0) ? Aext : (SRC == 1 ? g_cat1 : g_cat2);

    int t = threadIdx.x;
    int n0 = blockIdx.x * TN;
    int d0 = blockIdx.y * TD;
    int h  = blockIdx.z;
    const float* Wh = W + (size_t)h * K * Dtot;
    const int rg = t / (TD / NC);
    const int cg = t % (TD / NC);

    float acc[MR][NC];
#pragma unroll
    for (int i = 0; i < MR; i++)
#pragma unroll
        for (int j = 0; j < NC; j++) acc[i][j] = 0.f;

    for (int k0 = 0; k0 < K; k0 += TK) {
        for (int idx = t; idx < TN * (TK / 4); idx += 256) {
            int i_n = idx / (TK / 4);
            int k4  = idx % (TK / 4);
            float4 v = *(const float4*)&A[(size_t)(n0 + i_n) * K + k0 + 4 * k4];
            As[4 * k4 + 0][i_n] = v.x;
            As[4 * k4 + 1][i_n] = v.y;
            As[4 * k4 + 2][i_n] = v.z;
            As[4 * k4 + 3][i_n] = v.w;
        }
        for (int idx = t; idx < TK * (TD / 4); idx += 256) {
            int kk = idx / (TD / 4);
            int j4 = idx % (TD / 4);
            *(float4*)&Bs[kk][4 * j4] =
                *(const float4*)&Wh[(size_t)(k0 + kk) * Dtot + d0 + 4 * j4];
        }
        __syncthreads();
#pragma unroll
        for (int k = 0; k < TK; k++) {
            float a_[MR], b_[NC];
#pragma unroll
            for (int i = 0; i < MR; i++) a_[i] = As[k][rg * MR + i];
#pragma unroll
            for (int j = 0; j < NC; j++) b_[j] = Bs[k][cg * NC + j];
#pragma unroll
            for (int i = 0; i < MR; i++)
#pragma unroll
                for (int j = 0; j < NC; j++)
                    acc[i][j] = fmaf(a_[i], b_[j], acc[i][j]);
        }
        __syncthreads();
    }
    float* Ch = g_hf + (size_t)h * NNODES * Dtot;
#pragma unroll
    for (int i = 0; i < MR; i++)
#pragma unroll
        for (int j = 0; j < NC; j++)
            Ch[(size_t)(n0 + rg * MR + i) * Dtot + d0 + cg * NC + j] = acc[i][j];
}

// ---------------- scores ----------------
__global__ __launch_bounds__(256) void scores_k(const float* __restrict__ a, int D, int total) {
    int gid  = blockIdx.x * 8 + (threadIdx.x >> 5);
    int lane = threadIdx.x & 31;
    if (gid >= total) return;
    int h = gid / NNODES, n = gid % NNODES;
    const float* hr = g_hf + ((size_t)h * NNODES + n) * D;
    const float* a1 = a + (size_t)h * 2 * D;
    const float* a2 = a1 + D;
    float s1 = 0.f, s2 = 0.f;
    for (int d = lane; d < D; d += 32) {
        float v = hr[d];
        s1 += v * a1[d];
        s2 += v * a2[d];
    }
#pragma unroll
    for (int o = 16; o; o >>= 1) {
        s1 += __shfl_xor_sync(~0u, s1, o);
        s2 += __shfl_xor_sync(~0u, s2, o);
    }
    if (!lane) {
        int idx = h * NNODES + n;
        g_f1[idx]  = s1;
        g_f2[idx]  = s2;
        g_E1[idx]  = expf(s1);
        g_E1s[idx] = expf(0.2f * s1);
        g_E2[idx]  = expf(s2);
        g_E2s[idx] = expf(0.2f * s2);
    }
}

// ---------------- transpose + tf32 round: g_hf[h][n][d] -> g_hT[h][d][m] ----------------
template<int D>
__global__ __launch_bounds__(256) void transpose_tf32_k() {
    __shared__ float ts[32][33];
    int t  = threadIdx.x;
    int nt = blockIdx.x, dt = blockIdx.y, h = blockIdx.z;
    int r0 = t / 32, c = t % 32;
#pragma unroll
    for (int p = 0; p < 4; p++) {
        int r = p * 8 + r0;
        ts[r][c] = g_hf[((size_t)h * NNODES + nt * 32 + r) * D + dt * 32 + c];
    }
    __syncthreads();
#pragma unroll
    for (int p = 0; p < 4; p++) {
        int dr = p * 8 + r0;
        uint32_t v = tf32u(ts[c][dr]);
        size_t addr = ((size_t)h * D + dt * 32 + dr) * NNODES + nt * 32 + c;
        g_hT[addr] = __uint_as_float(v);
    }
}

// ---------------- tf32 mma masked-softmax aggregation ----------------
// CTA: 32 n-rows x 64 d-cols, 128 threads = 4 warps (2 Mg x 2 Ng).
// blockIdx = (n-tile, head, d-half). 3-stage cp.async ring, chunk = 64 m.
// B smem: [64 d][68 floats] per buf (stride-68 = conflict-free frag loads).
template<int D>
__global__ __launch_bounds__(128, 4) void aggM_k(const float* __restrict__ resid) {
    constexpr int NCH = NNODES / 64;
    constexpr int BSTRIDE = 68;                 // floats per d-row
    constexpr int BBUF = 64 * BSTRIDE * 4;      // 17408 B
    const int O_E  = 3 * BBUF;                  // 52224
    const int O_ZS = O_E + 3 * 768;             // 54528

    extern __shared__ __align__(16) char sm[];
    const uint32_t sb = smem_u32(sm);
    float* Zs = (float*)(sm + O_ZS);

    const int t = threadIdx.x, lane = t & 31, wid = t >> 5;
    const int Mg = wid >> 1, Ng = wid & 1;
    const int n0 = blockIdx.x * 32;
    const int head = blockIdx.y;
    const int dc0 = blockIdx.z * 64;
    const int headN = head * NNODES;
    const int rq  = lane >> 2;
    const int k0b = lane & 3;

    // row constants: 2 rows per thread (rq, rq+8) within Mg's 16-row tile
    float f1r[2], E1r[2], E1sr[2];
    const unsigned* adjrow[2];
#pragma unroll
    for (int i = 0; i < 2; i++) {
        int r = Mg * 16 + rq + i * 8;
        f1r[i]  = g_f1[headN + n0 + r];
        E1r[i]  = g_E1[headN + n0 + r];
        E1sr[i] = g_E1s[headN + n0 + r];
        adjrow[i] = &g_adjbits[(size_t)(n0 + r) * NW];
    }

    float acc[4][4];
#pragma unroll
    for (int a = 0; a < 4; a++)
#pragma unroll
        for (int q = 0; q < 4; q++) acc[a][q] = 0.f;
    float zacc[2] = {0.f, 0.f};

    auto fill = [&](int chunk, int buf) {
        // B tile: 64 d-rows x 64 m floats
        for (int idx = t; idx < 1024; idx += 128) {
            int row = idx >> 4, c16 = idx & 15;
            uint32_t dst = sb + (uint32_t)(buf * BBUF + row * (BSTRIDE * 4) + c16 * 16);
            size_t s = ((size_t)(head * D + dc0 + row)) * NNODES + chunk * 64 + c16 * 4;
            CP16(dst, (const void*)(g_hT + s));
        }
        if (t < 48) {
            int a = t >> 4, q = t & 15;
            const float* s = (a == 0 ? g_f2 : a == 1 ? g_E2 : g_E2s) +
                             headN + chunk * 64 + q * 4;
            uint32_t dst = sb + (uint32_t)(O_E + buf * 768 + a * 256 + q * 16);
            CP16(dst, (const void*)s);
        }
    };

    ull amask[2], amaskN[2];
#pragma unroll
    for (int i = 0; i < 2; i++) { amask[i] = *(const ull*)(adjrow[i]); amaskN[i] = amask[i]; }

    fill(0, 0); CP_COMMIT();
    fill(1, 1); CP_COMMIT();

    for (int c = 0; c < NCH; c++) {
        const int buf = c % 3;
        if (c == NCH - 1) CP_WAIT(0); else CP_WAIT(1);
        __syncthreads();
        if (c + 1 < NCH) {
#pragma unroll
            for (int i = 0; i < 2; i++)
                amaskN[i] = *(const ull*)(adjrow[i] + 2 * (c + 1));
        }
        const float* Bs   = (const float*)(sm + buf * BBUF);
        const float* f2c  = (const float*)(sm + O_E + buf * 768);
        const float* E2c  = f2c + 64;
        const float* E2sc = f2c + 128;

#pragma unroll
        for (int kt = 0; kt < 4; kt++) {
            // q -> m = kt*16 + q*4 + k0b ; half = q>>1
            float f2v[4], e2v[4], e2sv[4];
#pragma unroll
            for (int q = 0; q < 4; q++) {
                int mloc = kt * 16 + q * 4 + k0b;
                f2v[q] = f2c[mloc]; e2v[q] = E2c[mloc]; e2sv[q] = E2sc[mloc];
            }
            uint32_t afr[2][4];     // [half][a0..a3]
#pragma unroll
            for (int i = 0; i < 2; i++) {
                float w[4];
#pragma unroll
                for (int q = 0; q < 4; q++) {
                    float s = f1r[i] + f2v[q];
                    w[q] = (s >= 0.f) ? E1r[i] * e2v[q] : E1sr[i] * e2sv[q];
                    if (!((amask[i] >> (kt * 16 + q * 4 + k0b)) & 1ull)) w[q] = 0.f;
                }
                zacc[i] += (w[0] + w[1]) + (w[2] + w[3]);
                // half 0: k = k0b, k0b+4  -> q=0,1 ; half 1: q=2,3
                afr[0][i]     = tf32u(w[0]);
                afr[0][2 + i] = tf32u(w[1]);
                afr[1][i]     = tf32u(w[2]);
                afr[1][2 + i] = tf32u(w[3]);
            }
#pragma unroll
            for (int half = 0; half < 2; half++) {
                const int mb = kt * 16 + half * 8 + k0b;
#pragma unroll
                for (int ng = 0; ng < 4; ng++) {
                    const int drow = Ng * 32 + ng * 8 + rq;
                    float b0 = Bs[drow * BSTRIDE + mb];
                    float b1 = Bs[drow * BSTRIDE + mb + 4];
                    mma_tf32(acc[ng], afr[half][0], afr[half][1],
                             afr[half][2], afr[half][3],
                             __float_as_uint(b0), __float_as_uint(b1));
                }
            }
        }
#pragma unroll
        for (int i = 0; i < 2; i++) amask[i] = amaskN[i];
        if (c + 2 < NCH) { fill(c + 2, (c + 2) % 3); CP_COMMIT(); }
    }

    // Z reduce over lane quads (m partials); rows owned by lane quads
#pragma unroll
    for (int i = 0; i < 2; i++) {
        float z = zacc[i];
        z += __shfl_xor_sync(~0u, z, 1);
        z += __shfl_xor_sync(~0u, z, 2);
        if (Ng == 0 && (lane & 3) == 0) Zs[Mg * 16 + rq + i * 8] = 1.f / z;
    }
    __syncthreads();

    float* out = (D == 128) ? g_cat1 : g_cat2;
    const int ostr = (D == 128) ? 512 : 256;
#pragma unroll
    for (int i = 0; i < 2; i++) {
        int lr = Mg * 16 + rq + i * 8;
        int n  = n0 + lr;
        float zi = Zs[lr];
#pragma unroll
        for (int nt = 0; nt < 4; nt++) {
            int col = Ng * 32 + nt * 8 + (lane & 3) * 2;
            float v0 = acc[nt][2 * i]     * zi;
            float v1 = acc[nt][2 * i + 1] * zi;
            if (D == 128) {
                float2 rx = *(const float2*)&resid[(size_t)n * 128 + dc0 + col];
                v0 += rx.x; v1 += rx.y;
            }
            float2 o = {eluf(v0), eluf(v1)};
            *(float2*)&out[(size_t)n * ostr + head * D + dc0 + col] = o;
        }
    }
}

// ---------------- SIMT agg for layer 3 (D=16) ----------------
__device__ __forceinline__ ull dupf(float v) {
    ull r; asm("mov.b64 %0, {%1, %1};" : "=l"(r) : "f"(v)); return r;
}
__device__ __forceinline__ void ffma2(ull& acc, ull a, ull b) {
    asm("fma.rn.f32x2 %0, %1, %2, %0;" : "+l"(acc) : "l"(a), "l"(b));
}
__device__ __forceinline__ float2 unpack2(ull v) {
    float2 r; asm("mov.b64 {%0, %1}, %2;" : "=f"(r.x), "=f"(r.y) : "l"(v)); return r;
}

__global__ __launch_bounds__(128) void agg3_k() {
    const int D = 16, TN = 32, TM = 32, MR = 2, NC = 2;
    __shared__ __align__(16) float hs[2][TM][D];
    __shared__ __align__(16) float ws[2][TM][TN + 2];
    __shared__ float Zred[128];
    __shared__ float Zs[TN];

    const int t  = threadIdx.x;
    const int n0 = blockIdx.x * TN;
    const float* hfh = g_hf;

    const int rA = t % TN;
    const int G  = 128 / TN;
    const int g  = t / TN;
    const int MMPT = TM / G;

    const float rf1  = g_f1[n0 + rA];
    const float rE1  = g_E1[n0 + rA];
    const float rE1s = g_E1s[n0 + rA];
    float zacc = 0.f;

    const int rg = t / (D / NC);
    const int cg = t % (D / NC);

    ull acc[NC];
#pragma unroll
    for (int j = 0; j < NC; j++) acc[j] = 0ull;

    auto fill = [&](int wti, int buf) {
        int m0 = wti * TM;
        for (int idx = t; idx < TM * (D / 4); idx += 128) {
            int m  = idx / (D / 4);
            int dd = idx % (D / 4);
            *(float4*)&hs[buf][m][4 * dd] = *(const float4*)&hfh[(size_t)(m0 + m) * D + 4 * dd];
        }
        unsigned aw = g_adjbits[(size_t)(n0 + rA) * NW + wti];
#pragma unroll
        for (int j = 0; j < MMPT; j++) {
            int mm = g + G * j;
            float w = 0.f;
            if ((aw >> mm) & 1u) {
                float s = rf1 + g_f2[m0 + mm];
                w = (s >= 0.f) ? rE1 * g_E2[m0 + mm] : rE1s * g_E2s[m0 + mm];
            }
            ws[buf][mm][rA] = w;
            zacc += w;
        }
    };

    fill(0, 0);
    __syncthreads();
    const int NT = NNODES / TM;
    for (int mt = 0; mt < NT; mt++) {
        int cur = mt & 1;
        if (mt + 1 < NT) fill(mt + 1, cur ^ 1);
#pragma unroll
        for (int k = 0; k < TM; k++) {
            ull a2 = *(const ull*)&ws[cur][k][rg * MR];
#pragma unroll
            for (int j = 0; j < NC; j++) {
                ull bb = dupf(hs[cur][k][cg * NC + j]);
                ffma2(acc[j], a2, bb);
            }
        }
        __syncthreads();
    }
    Zred[t] = zacc;
    __syncthreads();
    if (t < TN) {
        float z = 0.f;
#pragma unroll
        for (int q = 0; q < G; q++) z += Zred[t + q * TN];
        Zs[t] = 1.f / z;
    }
    __syncthreads();
    {
        int lr0 = rg * MR;
        float zi0 = Zs[lr0], zi1 = Zs[lr0 + 1];
#pragma unroll
        for (int j = 0; j < NC; j++) {
            float2 v = unpack2(acc[j]);
            int d = cg * NC + j;
            g_h3[(size_t)(n0 + lr0) * 16 + d]     = eluf(v.x * zi0);
            g_h3[(size_t)(n0 + lr0 + 1) * 16 + d] = eluf(v.y * zi1);
        }
    }
}

// ---------------- final log-softmax ----------------
__global__ __launch_bounds__(256) void logsoftmax_k(float* __restrict__ out) {
    int n    = blockIdx.x * 8 + (threadIdx.x >> 5);
    int lane = threadIdx.x & 31;
    if (n >= NNODES) return;
    float v = (lane < 16) ? g_h3[n * 16 + lane] : -INFINITY;
    float m = v;
#pragma unroll
    for (int o = 16; o; o >>= 1) m = fmaxf(m, __shfl_xor_sync(~0u, m, o));
    float e = (lane < 16) ? expf(v - m) : 0.f;
    float s = e;
#pragma unroll
    for (int o = 16; o; o >>= 1) s += __shfl_xor_sync(~0u, s, o);
    if (lane < 16) out[n * 16 + lane] = v - m - logf(s);
}

// ---------------- launch ----------------
extern "C" void kernel_launch(void* const* d_in, const int* in_sizes, int n_in,
                              void* d_out, int out_size) {
    const float* x     = (const float*)d_in[0];
    const int*   adj   = (const int*)d_in[1];
    const float* W_in  = (const float*)d_in[2];
    const float* a_in  = (const float*)d_in[3];
    const float* W_hid = (const float*)d_in[4];
    const float* a_hid = (const float*)d_in[5];
    const float* W_out = (const float*)d_in[6];
    const float* a_out = (const float*)d_in[7];
    float* out = (float*)d_out;

    const int SMEM_AGG = 3 * 17408 + 3 * 768 + 128 + 16;   // 54672
    cudaFuncSetAttribute(aggM_k<128>, cudaFuncAttributeMaxDynamicSharedMemorySize, SMEM_AGG);
    cudaFuncSetAttribute(aggM_k<64>,  cudaFuncAttributeMaxDynamicSharedMemorySize, SMEM_AGG);

    pack_adj<<<(NNODES * NW + 255) / 256, 256>>>(adj);

    // Layer 1
    gemm_k<64, 64, 4, 4, 0><<<dim3(64, 2, 4), 256>>>(x, W_in, 128, 128);
    scores_k<<<(NHEADS * NNODES) / 8, 256>>>(a_in, 128, NHEADS * NNODES);
    transpose_tf32_k<128><<<dim3(128, 4, 4), 256>>>();
    aggM_k<128><<<dim3(128, 4, 2), 128, SMEM_AGG>>>(x);

    // Layer 2
    gemm_k<64, 64, 4, 4, 1><<<dim3(64, 1, 4), 256>>>(nullptr, W_hid, 512, 64);
    scores_k<<<(NHEADS * NNODES) / 8, 256>>>(a_hid, 64, NHEADS * NNODES);
    transpose_tf32_k<64><<<dim3(128, 2, 4), 256>>>();
    aggM_k<64><<<dim3(128, 4, 1), 128, SMEM_AGG>>>(nullptr);

    // Layer 3
    gemm_k<64, 16, 4, 1, 2><<<dim3(64, 1, 1), 256>>>(nullptr, W_out, 256, 16);
    scores_k<<<NNODES / 8, 256>>>(a_out, 16, NNODES);
    agg3_k<<<dim3(128, 1, 1), 128>>>();

    logsoftmax_k<<<NNODES / 8, 256>>>(out);
}